// round 6
// baseline (speedup 1.0000x reference)
#include <cuda_runtime.h>
#include <cuda_bf16.h>
#include <math.h>
#include <stdint.h>

#define BATCH 4
#define SEQ   2048
#define EMB   1024
#define NH    16
#define HD    64

// ---------------- scratch ----------------
__device__ float g_bias[65];
__device__ __nv_bfloat16 g_ah[(size_t)BATCH * SEQ * EMB];
__device__ __nv_bfloat16 g_al[(size_t)BATCH * SEQ * EMB];
__device__ __nv_bfloat16 g_bh[(size_t)3 * EMB * EMB];
__device__ __nv_bfloat16 g_bl[(size_t)3 * EMB * EMB];
#define HSZ ((size_t)BATCH * NH * SEQ * HD)
__device__ __nv_bfloat16 g_qh[HSZ], g_ql[HSZ];
__device__ __nv_bfloat16 g_kh[HSZ], g_kl[HSZ];
__device__ __nv_bfloat16 g_vh[HSZ], g_vl[HSZ];

// ---------------- PTX helpers ----------------
__device__ __forceinline__ uint32_t smem_u32(const void* p) {
    uint32_t a;
    asm("{ .reg .u64 t; cvta.to.shared.u64 t, %1; cvt.u32.u64 %0, t; }" : "=r"(a) : "l"(p));
    return a;
}
#define CP16(d, s)   asm volatile("cp.async.cg.shared.global [%0], [%1], 16;" :: "r"(d), "l"(s))
#define CP_COMMIT()  asm volatile("cp.async.commit_group;" ::: "memory")
#define CP_WAIT1()   asm volatile("cp.async.wait_group 1;" ::: "memory")
#define CP_WAIT0()   asm volatile("cp.async.wait_group 0;" ::: "memory")

#define LDSM4(r0, r1, r2, r3, a) \
    asm volatile("ldmatrix.sync.aligned.m8n8.x4.shared.b16 {%0,%1,%2,%3}, [%4];" \
        : "=r"(r0), "=r"(r1), "=r"(r2), "=r"(r3) : "r"(a))
#define LDSM4T(r0, r1, r2, r3, a) \
    asm volatile("ldmatrix.sync.aligned.m8n8.x4.trans.shared.b16 {%0,%1,%2,%3}, [%4];" \
        : "=r"(r0), "=r"(r1), "=r"(r2), "=r"(r3) : "r"(a))

#define MMA16816(d, a, b) \
    asm volatile("mma.sync.aligned.m16n8k16.row.col.f32.bf16.bf16.f32 " \
        "{%0,%1,%2,%3}, {%4,%5,%6,%7}, {%8,%9}, {%0,%1,%2,%3};" \
        : "+f"((d)[0]), "+f"((d)[1]), "+f"((d)[2]), "+f"((d)[3]) \
        : "r"((a)[0]), "r"((a)[1]), "r"((a)[2]), "r"((a)[3]), "r"((b)[0]), "r"((b)[1]))

// ---------------------------------------------------------------------------
__global__ void bias_kernel(const float* __restrict__ rel_bias) {
    int r = threadIdx.x;
    if (r < 65) {
        float s = 0.f;
        #pragma unroll
        for (int h = 0; h < NH; h++) s += rel_bias[r * NH + h];
        g_bias[r] = s * (1.0f / NH);
    }
}

// ---------------------------------------------------------------------------
__global__ __launch_bounds__(256) void split_kernel(
    const float* __restrict__ x, __nv_bfloat16* __restrict__ hi,
    __nv_bfloat16* __restrict__ lo, int n4)
{
    int i = blockIdx.x * blockDim.x + threadIdx.x;
    if (i >= n4) return;
    float4 v = ((const float4*)x)[i];
    __nv_bfloat16 h0 = __float2bfloat16(v.x), h1 = __float2bfloat16(v.y);
    __nv_bfloat16 h2 = __float2bfloat16(v.z), h3 = __float2bfloat16(v.w);
    __nv_bfloat162 H0 = {h0, h1}, H1 = {h2, h3};
    __nv_bfloat162 L0 = {__float2bfloat16(v.x - __bfloat162float(h0)),
                         __float2bfloat16(v.y - __bfloat162float(h1))};
    __nv_bfloat162 L1 = {__float2bfloat16(v.z - __bfloat162float(h2)),
                         __float2bfloat16(v.w - __bfloat162float(h3))};
    ((__nv_bfloat162*)hi)[i*2]   = H0;  ((__nv_bfloat162*)hi)[i*2+1] = H1;
    ((__nv_bfloat162*)lo)[i*2]   = L0;  ((__nv_bfloat162*)lo)[i*2+1] = L1;
}

// ---------------------------------------------------------------------------
// GEMM v3: C[M,N] = (Ah+Al)@(Bh+Bl)^T + bias.  256x128 tile, BK=64,
// 256 threads, 4x2 warp grid (64x64 warp tiles), 2-stage cp.async.
// QKVMODE: write per-head split bf16 q/k/v (q scaled 1/8) instead of fp32 C.
// ---------------------------------------------------------------------------
#define SAH 0u
#define SAL 36864u
#define SBH 73728u
#define SBL 92160u
#define SSG 110592u

template<bool QKVMODE>
__global__ __launch_bounds__(256) void gemm_v3(
    const __nv_bfloat16* __restrict__ Ah, const __nv_bfloat16* __restrict__ Al,
    const __nv_bfloat16* __restrict__ Bh, const __nv_bfloat16* __restrict__ Bl,
    const float* __restrict__ bias, float* __restrict__ C,
    __nv_bfloat16* __restrict__ qh, __nv_bfloat16* __restrict__ ql,
    __nv_bfloat16* __restrict__ kh, __nv_bfloat16* __restrict__ kl,
    __nv_bfloat16* __restrict__ vh, __nv_bfloat16* __restrict__ vl,
    int M, int N, int K)
{
    extern __shared__ char sm[];
    uint32_t smb = smem_u32(sm);
    const int t = threadIdx.x, lane = t & 31, wid = t >> 5;
    const int wm = wid >> 1, wn = wid & 1;
    const int m0 = blockIdx.y * 256, n0 = blockIdx.x * 128;

    auto load_stage = [&](int buf, int k0) {
        uint32_t d = smb + buf * SSG;
        #pragma unroll
        for (int c = 0; c < 8; c++) {
            int id = c * 256 + t;
            int row = id >> 3, ch = id & 7;
            uint32_t so = (uint32_t)(row * 144 + ch * 16);
            size_t go = (size_t)(m0 + row) * K + k0 + ch * 8;
            CP16(d + SAH + so, Ah + go);
            CP16(d + SAL + so, Al + go);
        }
        #pragma unroll
        for (int c = 0; c < 4; c++) {
            int id = c * 256 + t;
            int row = id >> 3, ch = id & 7;
            uint32_t so = (uint32_t)(row * 144 + ch * 16);
            size_t go = (size_t)(n0 + row) * K + k0 + ch * 8;
            CP16(d + SBH + so, Bh + go);
            CP16(d + SBL + so, Bl + go);
        }
    };

    float acc[4][8][4];
    #pragma unroll
    for (int i = 0; i < 4; i++)
        #pragma unroll
        for (int j = 0; j < 8; j++)
            #pragma unroll
            for (int v = 0; v < 4; v++) acc[i][j][v] = 0.f;

    const int NS = K >> 6;
    load_stage(0, 0);
    CP_COMMIT();

    for (int s = 0; s < NS; s++) {
        if (s + 1 < NS) { load_stage((s + 1) & 1, (s + 1) << 6); CP_COMMIT(); CP_WAIT1(); }
        else           { CP_WAIT0(); }
        __syncthreads();

        uint32_t base = smb + (s & 1) * SSG;

        #pragma unroll
        for (int ks = 0; ks < 4; ks++) {
            uint32_t a_ad[4], b_ad[4];
            #pragma unroll
            for (int mt = 0; mt < 4; mt++)
                a_ad[mt] = base + SAH + (uint32_t)((wm*64 + mt*16 + (lane & 15)) * 144
                                                   + ks*32 + (lane >> 4) * 16);
            #pragma unroll
            for (int p = 0; p < 4; p++)
                b_ad[p] = base + SBH + (uint32_t)((wn*64 + p*16 + (lane >> 4) * 8 + (lane & 7)) * 144
                                                  + ks*32 + ((lane >> 3) & 1) * 16);

            uint32_t af[4][4], xf[4][4], bf[8][2];
            #pragma unroll
            for (int mt = 0; mt < 4; mt++)
                LDSM4(af[mt][0], af[mt][1], af[mt][2], af[mt][3], a_ad[mt]);
            #pragma unroll
            for (int p = 0; p < 4; p++)
                LDSM4(bf[2*p][0], bf[2*p][1], bf[2*p+1][0], bf[2*p+1][1], b_ad[p]);
            #pragma unroll
            for (int mt = 0; mt < 4; mt++)
                #pragma unroll
                for (int j = 0; j < 8; j++) MMA16816(acc[mt][j], af[mt], bf[j]);
            #pragma unroll
            for (int mt = 0; mt < 4; mt++)
                LDSM4(xf[mt][0], xf[mt][1], xf[mt][2], xf[mt][3], a_ad[mt] + (SAL - SAH));
            #pragma unroll
            for (int mt = 0; mt < 4; mt++)
                #pragma unroll
                for (int j = 0; j < 8; j++) MMA16816(acc[mt][j], xf[mt], bf[j]);
            #pragma unroll
            for (int p = 0; p < 4; p++)
                LDSM4(bf[2*p][0], bf[2*p][1], bf[2*p+1][0], bf[2*p+1][1], b_ad[p] + (SBL - SBH));
            #pragma unroll
            for (int mt = 0; mt < 4; mt++)
                #pragma unroll
                for (int j = 0; j < 8; j++) MMA16816(acc[mt][j], af[mt], bf[j]);
        }
        __syncthreads();
    }

    #pragma unroll
    for (int mt = 0; mt < 4; mt++) {
        int m = m0 + wm*64 + mt*16 + (lane >> 2);
        #pragma unroll
        for (int j = 0; j < 8; j++) {
            int n = n0 + wn*64 + j*8 + (lane & 3) * 2;
            float b0 = bias[n], b1 = bias[n + 1];
            if (!QKVMODE) {
                *(float2*)(&C[(size_t)m * N + n]) =
                    make_float2(acc[mt][j][0] + b0, acc[mt][j][1] + b1);
                *(float2*)(&C[(size_t)(m + 8) * N + n]) =
                    make_float2(acc[mt][j][2] + b0, acc[mt][j][3] + b1);
            } else {
                int which = n >> 10;
                int hh = (n >> 6) & 15;
                int d = n & 63;
                __nv_bfloat16 *ph, *pl;
                float sc = 1.0f;
                if (which == 0)      { ph = qh; pl = ql; sc = 0.125f; }
                else if (which == 1) { ph = kh; pl = kl; }
                else                 { ph = vh; pl = vl; }
                #pragma unroll
                for (int r = 0; r < 2; r++) {
                    int mm = m + r * 8;
                    float v0 = (acc[mt][j][2*r]   + b0) * sc;
                    float v1 = (acc[mt][j][2*r+1] + b1) * sc;
                    size_t o = (((size_t)(mm >> 11) * NH + hh) * SEQ + (mm & 2047)) * HD + d;
                    __nv_bfloat16 h0 = __float2bfloat16(v0);
                    __nv_bfloat16 h1 = __float2bfloat16(v1);
                    __nv_bfloat162 H = {h0, h1};
                    __nv_bfloat162 L = {__float2bfloat16(v0 - __bfloat162float(h0)),
                                        __float2bfloat16(v1 - __bfloat162float(h1))};
                    *(__nv_bfloat162*)(ph + o) = H;
                    *(__nv_bfloat162*)(pl + o) = L;
                }
            }
        }
    }
}

// ---------------------------------------------------------------------------
// Flash attention v2: 128 threads (4 warps), 32 q-rows/warp (2 m16 subtiles),
// KV tile 64, 2-stage cp.async. K/V frags reused across both q-subtiles.
// Epilogue writes split bf16 ctx (ah/al) directly.
// ---------------------------------------------------------------------------
#define AQH 0u
#define AQL 18432u
#define AST 36864u
#define ASS 36864u
#define ALUT 110592u
#define ASMEM 110912u

__device__ __forceinline__ uint32_t packres(float a, float b, float& ra, float& rb) {
    __nv_bfloat162 h;
    h.x = __float2bfloat16(a); h.y = __float2bfloat16(b);
    ra = a - __bfloat162float(h.x);
    rb = b - __bfloat162float(h.y);
    return *(uint32_t*)&h;
}
__device__ __forceinline__ uint32_t packbf(float a, float b) {
    __nv_bfloat162 h;
    h.x = __float2bfloat16(a); h.y = __float2bfloat16(b);
    return *(uint32_t*)&h;
}

__global__ __launch_bounds__(128) void attn_hmma(
    const __nv_bfloat16* __restrict__ qh_g, const __nv_bfloat16* __restrict__ ql_g,
    const __nv_bfloat16* __restrict__ kh_g, const __nv_bfloat16* __restrict__ kl_g,
    const __nv_bfloat16* __restrict__ vh_g, const __nv_bfloat16* __restrict__ vl_g,
    __nv_bfloat16* __restrict__ ch_g, __nv_bfloat16* __restrict__ cl_g)
{
    extern __shared__ char sm[];
    uint32_t smb = smem_u32(sm);
    const int t = threadIdx.x, lane = t & 31, wq = t >> 5;
    const int q0 = blockIdx.x * 128, h = blockIdx.y, b = blockIdx.z;

    float* lut = (float*)(sm + ALUT);
    if (t < 65) lut[t] = g_bias[t];

    const size_t hb = ((size_t)b * NH + h) * SEQ;
    const size_t qg = (hb + q0) * HD;

    // Q: 2 arrays x 1024 16B chunks, 128 threads -> 8 each per array
    #pragma unroll
    for (int c = 0; c < 8; c++) {
        int id = c * 128 + t, row = id >> 3, ch = id & 7;
        uint32_t so = (uint32_t)(row * 144 + ch * 16);
        size_t go = qg + (size_t)row * 64 + ch * 8;
        CP16(smb + AQH + so, qh_g + go);
        CP16(smb + AQL + so, ql_g + go);
    }
    auto load_kv = [&](int buf, int j0) {
        uint32_t sb = smb + AST + (uint32_t)buf * ASS;
        size_t gb = (hb + j0) * HD;
        #pragma unroll
        for (int c = 0; c < 4; c++) {
            int id = c * 128 + t, row = id >> 3, ch = id & 7;
            uint32_t so = (uint32_t)(row * 144 + ch * 16);
            size_t go = gb + (size_t)row * 64 + ch * 8;
            CP16(sb + so,         kh_g + go);
            CP16(sb + 9216 + so,  kl_g + go);
            CP16(sb + 18432 + so, vh_g + go);
            CP16(sb + 27648 + so, vl_g + go);
        }
    };
    load_kv(0, 0);
    CP_COMMIT();

    uint32_t qhf[2][4][4], qlf[2][4][4];
    float oacc[2][8][4];
    #pragma unroll
    for (int qi = 0; qi < 2; qi++)
        #pragma unroll
        for (int i = 0; i < 8; i++)
            #pragma unroll
            for (int j = 0; j < 4; j++) oacc[qi][i][j] = 0.f;
    float mS[2][2], lS[2][2];
    #pragma unroll
    for (int qi = 0; qi < 2; qi++) { mS[qi][0] = mS[qi][1] = -1e30f; lS[qi][0] = lS[qi][1] = 0.f; }

    const int NT = SEQ / 64;

    for (int jt = 0; jt < NT; jt++) {
        if (jt + 1 < NT) { load_kv((jt + 1) & 1, (jt + 1) * 64); CP_COMMIT(); CP_WAIT1(); }
        else            { CP_WAIT0(); }
        __syncthreads();

        if (jt == 0) {
            #pragma unroll
            for (int qi = 0; qi < 2; qi++)
                #pragma unroll
                for (int ks = 0; ks < 4; ks++) {
                    uint32_t ar = (uint32_t)((wq*32 + qi*16 + ((lane>>3)&1)*8 + (lane&7)) * 144
                                             + ks*32 + ((lane>>4)&1)*16);
                    LDSM4(qhf[qi][ks][0], qhf[qi][ks][1], qhf[qi][ks][2], qhf[qi][ks][3], smb + AQH + ar);
                    LDSM4(qlf[qi][ks][0], qlf[qi][ks][1], qlf[qi][ks][2], qlf[qi][ks][3], smb + AQL + ar);
                }
        }

        uint32_t sb = smb + AST + (uint32_t)(jt & 1) * ASS;
        float sacc[2][8][4];
        #pragma unroll
        for (int qi = 0; qi < 2; qi++)
            #pragma unroll
            for (int i = 0; i < 8; i++)
                #pragma unroll
                for (int j = 0; j < 4; j++) sacc[qi][i][j] = 0.f;

        // S = Qh*Kh + Ql*Kh + Qh*Kl ; K frags shared by both q subtiles
        #pragma unroll
        for (int ks = 0; ks < 4; ks++) {
            #pragma unroll
            for (int p = 0; p < 4; p++) {
                uint32_t kr = (uint32_t)((p*16 + ((lane>>4)&1)*8 + (lane&7)) * 144
                                         + ks*32 + ((lane>>3)&1)*16);
                uint32_t h0, h1, h2, h3, l0, l1, l2, l3;
                LDSM4(h0, h1, h2, h3, sb + kr);
                LDSM4(l0, l1, l2, l3, sb + 9216 + kr);
                uint32_t bh0[2] = {h0, h1}, bh1[2] = {h2, h3};
                uint32_t bl0[2] = {l0, l1}, bl1[2] = {l2, l3};
                #pragma unroll
                for (int qi = 0; qi < 2; qi++) {
                    MMA16816(sacc[qi][2*p],   qhf[qi][ks], bh0);
                    MMA16816(sacc[qi][2*p],   qlf[qi][ks], bh0);
                    MMA16816(sacc[qi][2*p],   qhf[qi][ks], bl0);
                    MMA16816(sacc[qi][2*p+1], qhf[qi][ks], bh1);
                    MMA16816(sacc[qi][2*p+1], qlf[qi][ks], bh1);
                    MMA16816(sacc[qi][2*p+1], qhf[qi][ks], bl1);
                }
            }
        }

        // bias + online softmax, per q subtile
        #pragma unroll
        for (int qi = 0; qi < 2; qi++) {
            int qr = q0 + wq * 32 + qi * 16 + (lane >> 2);
            float mx0 = -1e30f, mx1 = -1e30f;
            #pragma unroll
            for (int nt = 0; nt < 8; nt++) {
                #pragma unroll
                for (int j = 0; j < 2; j++) {
                    int k = jt * 64 + nt * 8 + (lane & 3) * 2 + j;
                    int r = qr - k;
                    int r0 = r < -32 ? -32 : (r > 32 ? 32 : r);
                    int r1 = (r + 8) < -32 ? -32 : ((r + 8) > 32 ? 32 : (r + 8));
                    sacc[qi][nt][j]     += lut[r0 + 32];
                    sacc[qi][nt][2 + j] += lut[r1 + 32];
                    mx0 = fmaxf(mx0, sacc[qi][nt][j]);
                    mx1 = fmaxf(mx1, sacc[qi][nt][2 + j]);
                }
            }
            #pragma unroll
            for (int off = 1; off <= 2; off <<= 1) {
                mx0 = fmaxf(mx0, __shfl_xor_sync(0xffffffffu, mx0, off));
                mx1 = fmaxf(mx1, __shfl_xor_sync(0xffffffffu, mx1, off));
            }
            float mn0 = fmaxf(mS[qi][0], mx0), mn1 = fmaxf(mS[qi][1], mx1);
            float al0 = __expf(mS[qi][0] - mn0), al1 = __expf(mS[qi][1] - mn1);
            mS[qi][0] = mn0; mS[qi][1] = mn1;
            float s0 = 0.f, s1 = 0.f;
            #pragma unroll
            for (int nt = 0; nt < 8; nt++) {
                #pragma unroll
                for (int j = 0; j < 2; j++) {
                    float p0 = __expf(sacc[qi][nt][j] - mn0);
                    float p1 = __expf(sacc[qi][nt][2 + j] - mn1);
                    sacc[qi][nt][j] = p0;  sacc[qi][nt][2 + j] = p1;
                    s0 += p0;  s1 += p1;
                }
            }
            #pragma unroll
            for (int off = 1; off <= 2; off <<= 1) {
                s0 += __shfl_xor_sync(0xffffffffu, s0, off);
                s1 += __shfl_xor_sync(0xffffffffu, s1, off);
            }
            lS[qi][0] = lS[qi][0] * al0 + s0;
            lS[qi][1] = lS[qi][1] * al1 + s1;
            #pragma unroll
            for (int nt = 0; nt < 8; nt++) {
                oacc[qi][nt][0] *= al0;  oacc[qi][nt][1] *= al0;
                oacc[qi][nt][2] *= al1;  oacc[qi][nt][3] *= al1;
            }
        }

        // O += Ph*Vh + Pl*Vh + Ph*Vl ; V frags shared by both q subtiles
        #pragma unroll
        for (int ks = 0; ks < 4; ks++) {
            uint32_t ph[2][4], pl[2][4];
            #pragma unroll
            for (int qi = 0; qi < 2; qi++) {
                float ra, rb;
                ph[qi][0] = packres(sacc[qi][2*ks][0],   sacc[qi][2*ks][1],   ra, rb); pl[qi][0] = packbf(ra, rb);
                ph[qi][1] = packres(sacc[qi][2*ks][2],   sacc[qi][2*ks][3],   ra, rb); pl[qi][1] = packbf(ra, rb);
                ph[qi][2] = packres(sacc[qi][2*ks+1][0], sacc[qi][2*ks+1][1], ra, rb); pl[qi][2] = packbf(ra, rb);
                ph[qi][3] = packres(sacc[qi][2*ks+1][2], sacc[qi][2*ks+1][3], ra, rb); pl[qi][3] = packbf(ra, rb);
            }
            #pragma unroll
            for (int p = 0; p < 4; p++) {
                uint32_t vr = (uint32_t)((ks*16 + ((lane>>3)&1)*8 + (lane&7)) * 144
                                         + p*32 + ((lane>>4)&1)*16);
                uint32_t h0, h1, h2, h3, l0, l1, l2, l3;
                LDSM4T(h0, h1, h2, h3, sb + 18432 + vr);
                LDSM4T(l0, l1, l2, l3, sb + 27648 + vr);
                uint32_t bh0[2] = {h0, h1}, bh1[2] = {h2, h3};
                uint32_t bl0[2] = {l0, l1}, bl1[2] = {l2, l3};
                #pragma unroll
                for (int qi = 0; qi < 2; qi++) {
                    MMA16816(oacc[qi][2*p],   ph[qi], bh0);
                    MMA16816(oacc[qi][2*p],   pl[qi], bh0);
                    MMA16816(oacc[qi][2*p],   ph[qi], bl0);
                    MMA16816(oacc[qi][2*p+1], ph[qi], bh1);
                    MMA16816(oacc[qi][2*p+1], pl[qi], bh1);
                    MMA16816(oacc[qi][2*p+1], ph[qi], bl1);
                }
            }
        }
        __syncthreads();
    }

    // epilogue: write split bf16 ctx directly into ah/al layout [B*S, E]
    #pragma unroll
    for (int qi = 0; qi < 2; qi++) {
        float inv0 = 1.0f / lS[qi][0], inv1 = 1.0f / lS[qi][1];
        int qr = q0 + wq * 32 + qi * 16 + (lane >> 2);
        size_t r0 = ((size_t)b * SEQ + qr) * EMB + h * HD;
        #pragma unroll
        for (int nt = 0; nt < 8; nt++) {
            int d = nt * 8 + (lane & 3) * 2;
            float v0 = oacc[qi][nt][0] * inv0, v1 = oacc[qi][nt][1] * inv0;
            float v2 = oacc[qi][nt][2] * inv1, v3 = oacc[qi][nt][3] * inv1;
            float ra, rb;
            uint32_t H0 = packres(v0, v1, ra, rb), L0 = packbf(ra, rb);
            *(uint32_t*)(ch_g + r0 + d) = H0;
            *(uint32_t*)(cl_g + r0 + d) = L0;
            uint32_t H1 = packres(v2, v3, ra, rb), L1 = packbf(ra, rb);
            *(uint32_t*)(ch_g + r0 + (size_t)8 * EMB + d) = H1;
            *(uint32_t*)(cl_g + r0 + (size_t)8 * EMB + d) = L1;
        }
    }
}

// ---------------------------------------------------------------------------
extern "C" void kernel_launch(void* const* d_in, const int* in_sizes, int n_in,
                              void* d_out, int out_size)
{
    const float* x  = (const float*)d_in[0];
    const float* w1 = (const float*)d_in[1];
    const float* b1 = (const float*)d_in[2];
    const float* w2 = (const float*)d_in[3];
    const float* b2 = (const float*)d_in[4];
    const float* rb = (const float*)d_in[5];
    float* out = (float*)d_out;

    __nv_bfloat16 *ah, *al, *bh, *bl, *qh, *ql, *kh, *kl, *vh, *vl;
    cudaGetSymbolAddress((void**)&ah, g_ah);
    cudaGetSymbolAddress((void**)&al, g_al);
    cudaGetSymbolAddress((void**)&bh, g_bh);
    cudaGetSymbolAddress((void**)&bl, g_bl);
    cudaGetSymbolAddress((void**)&qh, g_qh);
    cudaGetSymbolAddress((void**)&ql, g_ql);
    cudaGetSymbolAddress((void**)&kh, g_kh);
    cudaGetSymbolAddress((void**)&kl, g_kl);
    cudaGetSymbolAddress((void**)&vh, g_vh);
    cudaGetSymbolAddress((void**)&vl, g_vl);

    const int MM = BATCH * SEQ;
    const size_t gemm_shm = 2 * (size_t)SSG;    // 221184 B
    cudaFuncSetAttribute(gemm_v3<true>,  cudaFuncAttributeMaxDynamicSharedMemorySize, (int)gemm_shm);
    cudaFuncSetAttribute(gemm_v3<false>, cudaFuncAttributeMaxDynamicSharedMemorySize, (int)gemm_shm);
    cudaFuncSetAttribute(attn_hmma, cudaFuncAttributeMaxDynamicSharedMemorySize, (int)ASMEM);

    bias_kernel<<<1, 96>>>(rb);

    {   // split x, w1
        int n4 = MM * EMB / 4;
        split_kernel<<<(n4 + 255) / 256, 256>>>(x, ah, al, n4);
        n4 = 3 * EMB * EMB / 4;
        split_kernel<<<(n4 + 255) / 256, 256>>>(w1, bh, bl, n4);
    }
    {   // QKV projection, fused per-head split epilogue
        dim3 g(3 * EMB / 128, MM / 256);
        gemm_v3<true><<<g, 256, gemm_shm>>>(ah, al, bh, bl, b1, nullptr,
                                            qh, ql, kh, kl, vh, vl,
                                            MM, 3 * EMB, EMB);
    }
    {   // attention, fused ctx-split epilogue (writes ah/al)
        dim3 g(SEQ / 128, NH, BATCH);
        attn_hmma<<<g, 128, ASMEM>>>(qh, ql, kh, kl, vh, vl, ah, al);
    }
    {   // split w2; out projection
        int n4 = EMB * EMB / 4;
        split_kernel<<<(n4 + 255) / 256, 256>>>(w2, bh, bl, n4);
        dim3 g(EMB / 128, MM / 256);
        gemm_v3<false><<<g, 256, gemm_shm>>>(ah, al, bh, bl, b2, out,
                                             nullptr, nullptr, nullptr, nullptr, nullptr, nullptr,
                                             MM, EMB, EMB);
    }
}

// round 7
// speedup vs baseline: 1.4675x; 1.4675x over previous
#include <cuda_runtime.h>
#include <cuda_bf16.h>
#include <math.h>
#include <stdint.h>

#define BATCH 4
#define SEQ   2048
#define EMB   1024
#define NH    16
#define HD    64

// ---------------- scratch ----------------
__device__ float g_bias[65];
__device__ __nv_bfloat16 g_ah[(size_t)BATCH * SEQ * EMB];
__device__ __nv_bfloat16 g_al[(size_t)BATCH * SEQ * EMB];
__device__ __nv_bfloat16 g_bh[(size_t)3 * EMB * EMB];
__device__ __nv_bfloat16 g_bl[(size_t)3 * EMB * EMB];
#define HSZ ((size_t)BATCH * NH * SEQ * HD)
__device__ __nv_bfloat16 g_qh[HSZ], g_ql[HSZ];
__device__ __nv_bfloat16 g_kh[HSZ], g_kl[HSZ];
__device__ __nv_bfloat16 g_vh[HSZ], g_vl[HSZ];

// ---------------- PTX helpers ----------------
__device__ __forceinline__ uint32_t smem_u32(const void* p) {
    uint32_t a;
    asm("{ .reg .u64 t; cvta.to.shared.u64 t, %1; cvt.u32.u64 %0, t; }" : "=r"(a) : "l"(p));
    return a;
}
#define CP16(d, s)   asm volatile("cp.async.cg.shared.global [%0], [%1], 16;" :: "r"(d), "l"(s))
#define CP_COMMIT()  asm volatile("cp.async.commit_group;" ::: "memory")
#define CP_WAIT1()   asm volatile("cp.async.wait_group 1;" ::: "memory")
#define CP_WAIT0()   asm volatile("cp.async.wait_group 0;" ::: "memory")

#define LDSM4(r0, r1, r2, r3, a) \
    asm volatile("ldmatrix.sync.aligned.m8n8.x4.shared.b16 {%0,%1,%2,%3}, [%4];" \
        : "=r"(r0), "=r"(r1), "=r"(r2), "=r"(r3) : "r"(a))
#define LDSM4T(r0, r1, r2, r3, a) \
    asm volatile("ldmatrix.sync.aligned.m8n8.x4.trans.shared.b16 {%0,%1,%2,%3}, [%4];" \
        : "=r"(r0), "=r"(r1), "=r"(r2), "=r"(r3) : "r"(a))

#define MMA16816(d, a, b) \
    asm volatile("mma.sync.aligned.m16n8k16.row.col.f32.bf16.bf16.f32 " \
        "{%0,%1,%2,%3}, {%4,%5,%6,%7}, {%8,%9}, {%0,%1,%2,%3};" \
        : "+f"((d)[0]), "+f"((d)[1]), "+f"((d)[2]), "+f"((d)[3]) \
        : "r"((a)[0]), "r"((a)[1]), "r"((a)[2]), "r"((a)[3]), "r"((b)[0]), "r"((b)[1]))

// ---------------------------------------------------------------------------
__global__ void bias_kernel(const float* __restrict__ rel_bias) {
    int r = threadIdx.x;
    if (r < 65) {
        float s = 0.f;
        #pragma unroll
        for (int h = 0; h < NH; h++) s += rel_bias[r * NH + h];
        g_bias[r] = s * (1.0f / NH);
    }
}

// ---------------------------------------------------------------------------
__global__ __launch_bounds__(256) void split_kernel(
    const float* __restrict__ x, __nv_bfloat16* __restrict__ hi,
    __nv_bfloat16* __restrict__ lo, int n4)
{
    int i = blockIdx.x * blockDim.x + threadIdx.x;
    if (i >= n4) return;
    float4 v = ((const float4*)x)[i];
    __nv_bfloat16 h0 = __float2bfloat16(v.x), h1 = __float2bfloat16(v.y);
    __nv_bfloat16 h2 = __float2bfloat16(v.z), h3 = __float2bfloat16(v.w);
    __nv_bfloat162 H0 = {h0, h1}, H1 = {h2, h3};
    __nv_bfloat162 L0 = {__float2bfloat16(v.x - __bfloat162float(h0)),
                         __float2bfloat16(v.y - __bfloat162float(h1))};
    __nv_bfloat162 L1 = {__float2bfloat16(v.z - __bfloat162float(h2)),
                         __float2bfloat16(v.w - __bfloat162float(h3))};
    ((__nv_bfloat162*)hi)[i*2]   = H0;  ((__nv_bfloat162*)hi)[i*2+1] = H1;
    ((__nv_bfloat162*)lo)[i*2]   = L0;  ((__nv_bfloat162*)lo)[i*2+1] = L1;
}

// ---------------------------------------------------------------------------
// HMMA split-bf16 GEMM (R5 config): 128x128 tile, BK=32, 128 threads,
// 2x2 warp grid (64x64 warp tiles), 2 CTAs/SM.
// QKVMODE: epilogue writes per-head split bf16 q/k/v (q scaled 1/8).
// ---------------------------------------------------------------------------
#define TIL 10240
#define STG (4*TIL)

template<bool QKVMODE>
__global__ __launch_bounds__(128) void gemm_hmma(
    const __nv_bfloat16* __restrict__ Ah, const __nv_bfloat16* __restrict__ Al,
    const __nv_bfloat16* __restrict__ Bh, const __nv_bfloat16* __restrict__ Bl,
    const float* __restrict__ bias, float* __restrict__ C,
    __nv_bfloat16* __restrict__ qh, __nv_bfloat16* __restrict__ ql,
    __nv_bfloat16* __restrict__ kh, __nv_bfloat16* __restrict__ kl,
    __nv_bfloat16* __restrict__ vh, __nv_bfloat16* __restrict__ vl,
    int M, int N, int K)
{
    extern __shared__ char sm[];
    uint32_t smb = smem_u32(sm);
    const int t = threadIdx.x;
    const int lane = t & 31, wid = t >> 5;
    const int wm = wid >> 1, wn = wid & 1;
    const int m0 = blockIdx.y * 128, n0 = blockIdx.x * 128;

    auto load_stage = [&](int buf, int k0) {
        uint32_t d = smb + buf * STG;
        #pragma unroll
        for (int c = 0; c < 4; c++) {
            int id = c * 128 + t;
            int row = id >> 2, ch = id & 3;
            uint32_t so = (uint32_t)(row * 80 + ch * 16);
            size_t ao = (size_t)(m0 + row) * K + k0 + ch * 8;
            size_t bo = (size_t)(n0 + row) * K + k0 + ch * 8;
            CP16(d + so,           Ah + ao);
            CP16(d + TIL + so,     Al + ao);
            CP16(d + 2*TIL + so,   Bh + bo);
            CP16(d + 3*TIL + so,   Bl + bo);
        }
    };

    float acc[4][8][4];
    #pragma unroll
    for (int i = 0; i < 4; i++)
        #pragma unroll
        for (int j = 0; j < 8; j++)
            #pragma unroll
            for (int v = 0; v < 4; v++) acc[i][j][v] = 0.f;

    const int NS = K >> 5;
    load_stage(0, 0);
    CP_COMMIT();

    for (int s = 0; s < NS; s++) {
        if (s + 1 < NS) { load_stage((s + 1) & 1, (s + 1) << 5); CP_COMMIT(); CP_WAIT1(); }
        else           { CP_WAIT0(); }
        __syncthreads();

        uint32_t abase = smb + (s & 1) * STG;
        uint32_t bbase = abase + 2 * TIL;

        #pragma unroll
        for (int ks = 0; ks < 2; ks++) {
            uint32_t a_ad[4], b_ad[4];
            #pragma unroll
            for (int mt = 0; mt < 4; mt++)
                a_ad[mt] = abase + (uint32_t)((wm*64 + mt*16 + (lane & 15)) * 80
                                              + ks*32 + (lane >> 4) * 16);
            #pragma unroll
            for (int p = 0; p < 4; p++)
                b_ad[p] = bbase + (uint32_t)((wn*64 + p*16 + (lane >> 4) * 8 + (lane & 7)) * 80
                                             + ks*32 + ((lane >> 3) & 1) * 16);

            uint32_t af[4][4], xf[4][4], bf[8][2];
            #pragma unroll
            for (int mt = 0; mt < 4; mt++)
                LDSM4(af[mt][0], af[mt][1], af[mt][2], af[mt][3], a_ad[mt]);
            #pragma unroll
            for (int p = 0; p < 4; p++)
                LDSM4(bf[2*p][0], bf[2*p][1], bf[2*p+1][0], bf[2*p+1][1], b_ad[p]);
            #pragma unroll
            for (int mt = 0; mt < 4; mt++)
                #pragma unroll
                for (int j = 0; j < 8; j++) MMA16816(acc[mt][j], af[mt], bf[j]);
            #pragma unroll
            for (int mt = 0; mt < 4; mt++)
                LDSM4(xf[mt][0], xf[mt][1], xf[mt][2], xf[mt][3], a_ad[mt] + TIL);
            #pragma unroll
            for (int mt = 0; mt < 4; mt++)
                #pragma unroll
                for (int j = 0; j < 8; j++) MMA16816(acc[mt][j], xf[mt], bf[j]);
            #pragma unroll
            for (int p = 0; p < 4; p++)
                LDSM4(bf[2*p][0], bf[2*p][1], bf[2*p+1][0], bf[2*p+1][1], b_ad[p] + TIL);
            #pragma unroll
            for (int mt = 0; mt < 4; mt++)
                #pragma unroll
                for (int j = 0; j < 8; j++) MMA16816(acc[mt][j], af[mt], bf[j]);
        }
        __syncthreads();
    }

    #pragma unroll
    for (int mt = 0; mt < 4; mt++) {
        int m = m0 + wm*64 + mt*16 + (lane >> 2);
        #pragma unroll
        for (int j = 0; j < 8; j++) {
            int n = n0 + wn*64 + j*8 + (lane & 3) * 2;
            float b0 = bias[n], b1 = bias[n + 1];
            if (!QKVMODE) {
                *(float2*)(&C[(size_t)m * N + n]) =
                    make_float2(acc[mt][j][0] + b0, acc[mt][j][1] + b1);
                *(float2*)(&C[(size_t)(m + 8) * N + n]) =
                    make_float2(acc[mt][j][2] + b0, acc[mt][j][3] + b1);
            } else {
                int which = n >> 10;
                int hh = (n >> 6) & 15;
                int d = n & 63;
                __nv_bfloat16 *ph, *pl;
                float sc = 1.0f;
                if (which == 0)      { ph = qh; pl = ql; sc = 0.125f; }
                else if (which == 1) { ph = kh; pl = kl; }
                else                 { ph = vh; pl = vl; }
                #pragma unroll
                for (int r = 0; r < 2; r++) {
                    int mm = m + r * 8;
                    float v0 = (acc[mt][j][2*r]   + b0) * sc;
                    float v1 = (acc[mt][j][2*r+1] + b1) * sc;
                    size_t o = (((size_t)(mm >> 11) * NH + hh) * SEQ + (mm & 2047)) * HD + d;
                    __nv_bfloat16 h0 = __float2bfloat16(v0);
                    __nv_bfloat16 h1 = __float2bfloat16(v1);
                    __nv_bfloat162 H = {h0, h1};
                    __nv_bfloat162 L = {__float2bfloat16(v0 - __bfloat162float(h0)),
                                        __float2bfloat16(v1 - __bfloat162float(h1))};
                    *(__nv_bfloat162*)(ph + o) = H;
                    *(__nv_bfloat162*)(pl + o) = L;
                }
            }
        }
    }
}

// ---------------------------------------------------------------------------
// HMMA flash attention (R4 config: 256 threads, 8 warps x m16), fused
// ctx-split epilogue writing bf16 ah/al directly.
// ---------------------------------------------------------------------------
#define AQH 0u
#define AQL 18432u
#define AST 36864u
#define ASS 36864u
#define ALUT 110592u
#define ASMEM 110912u

__device__ __forceinline__ uint32_t packres(float a, float b, float& ra, float& rb) {
    __nv_bfloat162 h;
    h.x = __float2bfloat16(a); h.y = __float2bfloat16(b);
    ra = a - __bfloat162float(h.x);
    rb = b - __bfloat162float(h.y);
    return *(uint32_t*)&h;
}
__device__ __forceinline__ uint32_t packbf(float a, float b) {
    __nv_bfloat162 h;
    h.x = __float2bfloat16(a); h.y = __float2bfloat16(b);
    return *(uint32_t*)&h;
}

__global__ __launch_bounds__(256) void attn_hmma(
    const __nv_bfloat16* __restrict__ qh_g, const __nv_bfloat16* __restrict__ ql_g,
    const __nv_bfloat16* __restrict__ kh_g, const __nv_bfloat16* __restrict__ kl_g,
    const __nv_bfloat16* __restrict__ vh_g, const __nv_bfloat16* __restrict__ vl_g,
    __nv_bfloat16* __restrict__ ch_g, __nv_bfloat16* __restrict__ cl_g)
{
    extern __shared__ char sm[];
    uint32_t smb = smem_u32(sm);
    const int t = threadIdx.x, lane = t & 31, wq = t >> 5;
    const int q0 = blockIdx.x * 128, h = blockIdx.y, b = blockIdx.z;

    float* lut = (float*)(sm + ALUT);
    if (t < 65) lut[t] = g_bias[t];

    const size_t hb = ((size_t)b * NH + h) * SEQ;
    const size_t qg = (hb + q0) * HD;

    #pragma unroll
    for (int i = 0; i < 4; i++) {
        int id = t * 4 + i, row = id >> 3, ch = id & 7;
        uint32_t so = (uint32_t)(row * 144 + ch * 16);
        size_t go = qg + (size_t)row * 64 + ch * 8;
        CP16(smb + AQH + so, qh_g + go);
        CP16(smb + AQL + so, ql_g + go);
    }
    auto load_kv = [&](int buf, int j0) {
        uint32_t sb = smb + AST + (uint32_t)buf * ASS;
        size_t gb = (hb + j0) * HD;
        #pragma unroll
        for (int i = 0; i < 2; i++) {
            int id = t * 2 + i, row = id >> 3, ch = id & 7;
            uint32_t so = (uint32_t)(row * 144 + ch * 16);
            size_t go = gb + (size_t)row * 64 + ch * 8;
            CP16(sb + so,         kh_g + go);
            CP16(sb + 9216 + so,  kl_g + go);
            CP16(sb + 18432 + so, vh_g + go);
            CP16(sb + 27648 + so, vl_g + go);
        }
    };
    load_kv(0, 0);
    CP_COMMIT();

    uint32_t qhf[4][4], qlf[4][4];
    float oacc[8][4];
    #pragma unroll
    for (int i = 0; i < 8; i++)
        #pragma unroll
        for (int j = 0; j < 4; j++) oacc[i][j] = 0.f;
    float mrow0 = -1e30f, mrow1 = -1e30f, lrow0 = 0.f, lrow1 = 0.f;

    const int qr0 = q0 + wq * 16 + (lane >> 2);
    const int NT = SEQ / 64;

    for (int jt = 0; jt < NT; jt++) {
        if (jt + 1 < NT) { load_kv((jt + 1) & 1, (jt + 1) * 64); CP_COMMIT(); CP_WAIT1(); }
        else            { CP_WAIT0(); }
        __syncthreads();

        if (jt == 0) {
            #pragma unroll
            for (int ks = 0; ks < 4; ks++) {
                uint32_t ar = (uint32_t)((wq*16 + ((lane>>3)&1)*8 + (lane&7)) * 144
                                         + ks*32 + ((lane>>4)&1)*16);
                LDSM4(qhf[ks][0], qhf[ks][1], qhf[ks][2], qhf[ks][3], smb + AQH + ar);
                LDSM4(qlf[ks][0], qlf[ks][1], qlf[ks][2], qlf[ks][3], smb + AQL + ar);
            }
        }

        uint32_t sb = smb + AST + (uint32_t)(jt & 1) * ASS;
        float sacc[8][4];
        #pragma unroll
        for (int i = 0; i < 8; i++)
            #pragma unroll
            for (int j = 0; j < 4; j++) sacc[i][j] = 0.f;

        #pragma unroll
        for (int ks = 0; ks < 4; ks++) {
            #pragma unroll
            for (int p = 0; p < 4; p++) {
                uint32_t kr = (uint32_t)((p*16 + ((lane>>4)&1)*8 + (lane&7)) * 144
                                         + ks*32 + ((lane>>3)&1)*16);
                uint32_t h0, h1, h2, h3, l0, l1, l2, l3;
                LDSM4(h0, h1, h2, h3, sb + kr);
                LDSM4(l0, l1, l2, l3, sb + 9216 + kr);
                uint32_t bh0[2] = {h0, h1}, bh1[2] = {h2, h3};
                uint32_t bl0[2] = {l0, l1}, bl1[2] = {l2, l3};
                MMA16816(sacc[2*p],   qhf[ks], bh0);
                MMA16816(sacc[2*p],   qlf[ks], bh0);
                MMA16816(sacc[2*p],   qhf[ks], bl0);
                MMA16816(sacc[2*p+1], qhf[ks], bh1);
                MMA16816(sacc[2*p+1], qlf[ks], bh1);
                MMA16816(sacc[2*p+1], qhf[ks], bl1);
            }
        }

        float mx0 = -1e30f, mx1 = -1e30f;
        #pragma unroll
        for (int nt = 0; nt < 8; nt++) {
            #pragma unroll
            for (int j = 0; j < 2; j++) {
                int k = jt * 64 + nt * 8 + (lane & 3) * 2 + j;
                int r = qr0 - k;
                int r0 = r < -32 ? -32 : (r > 32 ? 32 : r);
                int r1 = (r + 8) < -32 ? -32 : ((r + 8) > 32 ? 32 : (r + 8));
                sacc[nt][j]     += lut[r0 + 32];
                sacc[nt][2 + j] += lut[r1 + 32];
                mx0 = fmaxf(mx0, sacc[nt][j]);
                mx1 = fmaxf(mx1, sacc[nt][2 + j]);
            }
        }
        #pragma unroll
        for (int off = 1; off <= 2; off <<= 1) {
            mx0 = fmaxf(mx0, __shfl_xor_sync(0xffffffffu, mx0, off));
            mx1 = fmaxf(mx1, __shfl_xor_sync(0xffffffffu, mx1, off));
        }
        float mn0 = fmaxf(mrow0, mx0), mn1 = fmaxf(mrow1, mx1);
        float al0 = __expf(mrow0 - mn0), al1 = __expf(mrow1 - mn1);
        mrow0 = mn0; mrow1 = mn1;
        float s0 = 0.f, s1 = 0.f;
        #pragma unroll
        for (int nt = 0; nt < 8; nt++) {
            #pragma unroll
            for (int j = 0; j < 2; j++) {
                float p0 = __expf(sacc[nt][j] - mn0);
                float p1 = __expf(sacc[nt][2 + j] - mn1);
                sacc[nt][j] = p0;  sacc[nt][2 + j] = p1;
                s0 += p0;  s1 += p1;
            }
        }
        #pragma unroll
        for (int off = 1; off <= 2; off <<= 1) {
            s0 += __shfl_xor_sync(0xffffffffu, s0, off);
            s1 += __shfl_xor_sync(0xffffffffu, s1, off);
        }
        lrow0 = lrow0 * al0 + s0;
        lrow1 = lrow1 * al1 + s1;
        #pragma unroll
        for (int nt = 0; nt < 8; nt++) {
            oacc[nt][0] *= al0;  oacc[nt][1] *= al0;
            oacc[nt][2] *= al1;  oacc[nt][3] *= al1;
        }

        #pragma unroll
        for (int ks = 0; ks < 4; ks++) {
            uint32_t ph[4], pl[4];
            float ra, rb;
            ph[0] = packres(sacc[2*ks][0],   sacc[2*ks][1],   ra, rb); pl[0] = packbf(ra, rb);
            ph[1] = packres(sacc[2*ks][2],   sacc[2*ks][3],   ra, rb); pl[1] = packbf(ra, rb);
            ph[2] = packres(sacc[2*ks+1][0], sacc[2*ks+1][1], ra, rb); pl[2] = packbf(ra, rb);
            ph[3] = packres(sacc[2*ks+1][2], sacc[2*ks+1][3], ra, rb); pl[3] = packbf(ra, rb);
            #pragma unroll
            for (int p = 0; p < 4; p++) {
                uint32_t vr = (uint32_t)((ks*16 + ((lane>>3)&1)*8 + (lane&7)) * 144
                                         + p*32 + ((lane>>4)&1)*16);
                uint32_t h0, h1, h2, h3, l0, l1, l2, l3;
                LDSM4T(h0, h1, h2, h3, sb + 18432 + vr);
                LDSM4T(l0, l1, l2, l3, sb + 27648 + vr);
                uint32_t bh0[2] = {h0, h1}, bh1[2] = {h2, h3};
                uint32_t bl0[2] = {l0, l1}, bl1[2] = {l2, l3};
                MMA16816(oacc[2*p],   ph, bh0);
                MMA16816(oacc[2*p],   pl, bh0);
                MMA16816(oacc[2*p],   ph, bl0);
                MMA16816(oacc[2*p+1], ph, bh1);
                MMA16816(oacc[2*p+1], pl, bh1);
                MMA16816(oacc[2*p+1], ph, bl1);
            }
        }
        __syncthreads();
    }

    // fused ctx-split epilogue: write bf16 hi/lo ctx in [B*S, E] layout
    float inv0 = 1.0f / lrow0, inv1 = 1.0f / lrow1;
    size_t row0 = ((size_t)b * SEQ + qr0) * EMB + h * HD;
    #pragma unroll
    for (int nt = 0; nt < 8; nt++) {
        int d = nt * 8 + (lane & 3) * 2;
        float v0 = oacc[nt][0] * inv0, v1 = oacc[nt][1] * inv0;
        float v2 = oacc[nt][2] * inv1, v3 = oacc[nt][3] * inv1;
        float ra, rb;
        uint32_t H0 = packres(v0, v1, ra, rb), L0 = packbf(ra, rb);
        *(uint32_t*)(ch_g + row0 + d) = H0;
        *(uint32_t*)(cl_g + row0 + d) = L0;
        uint32_t H1 = packres(v2, v3, ra, rb), L1 = packbf(ra, rb);
        *(uint32_t*)(ch_g + row0 + (size_t)8 * EMB + d) = H1;
        *(uint32_t*)(cl_g + row0 + (size_t)8 * EMB + d) = L1;
    }
}

// ---------------------------------------------------------------------------
extern "C" void kernel_launch(void* const* d_in, const int* in_sizes, int n_in,
                              void* d_out, int out_size)
{
    const float* x  = (const float*)d_in[0];
    const float* w1 = (const float*)d_in[1];
    const float* b1 = (const float*)d_in[2];
    const float* w2 = (const float*)d_in[3];
    const float* b2 = (const float*)d_in[4];
    const float* rb = (const float*)d_in[5];
    float* out = (float*)d_out;

    __nv_bfloat16 *ah, *al, *bh, *bl, *qh, *ql, *kh, *kl, *vh, *vl;
    cudaGetSymbolAddress((void**)&ah, g_ah);
    cudaGetSymbolAddress((void**)&al, g_al);
    cudaGetSymbolAddress((void**)&bh, g_bh);
    cudaGetSymbolAddress((void**)&bl, g_bl);
    cudaGetSymbolAddress((void**)&qh, g_qh);
    cudaGetSymbolAddress((void**)&ql, g_ql);
    cudaGetSymbolAddress((void**)&kh, g_kh);
    cudaGetSymbolAddress((void**)&kl, g_kl);
    cudaGetSymbolAddress((void**)&vh, g_vh);
    cudaGetSymbolAddress((void**)&vl, g_vl);

    const int MM = BATCH * SEQ;
    const size_t gemm_shm = 2 * (size_t)STG;   // 81920 B
    cudaFuncSetAttribute(gemm_hmma<true>,  cudaFuncAttributeMaxDynamicSharedMemorySize, (int)gemm_shm);
    cudaFuncSetAttribute(gemm_hmma<false>, cudaFuncAttributeMaxDynamicSharedMemorySize, (int)gemm_shm);
    cudaFuncSetAttribute(attn_hmma, cudaFuncAttributeMaxDynamicSharedMemorySize, (int)ASMEM);

    bias_kernel<<<1, 96>>>(rb);

    {   // split x, w1
        int n4 = MM * EMB / 4;
        split_kernel<<<(n4 + 255) / 256, 256>>>(x, ah, al, n4);
        n4 = 3 * EMB * EMB / 4;
        split_kernel<<<(n4 + 255) / 256, 256>>>(w1, bh, bl, n4);
    }
    {   // QKV projection with fused per-head split epilogue
        dim3 g(3 * EMB / 128, MM / 128);
        gemm_hmma<true><<<g, 128, gemm_shm>>>(ah, al, bh, bl, b1, nullptr,
                                              qh, ql, kh, kl, vh, vl,
                                              MM, 3 * EMB, EMB);
    }
    {   // attention with fused ctx-split epilogue (writes ah/al)
        dim3 g(SEQ / 128, NH, BATCH);
        attn_hmma<<<g, 256, ASMEM>>>(qh, ql, kh, kl, vh, vl, ah, al);
    }
    {   // split w2; out projection
        int n4 = EMB * EMB / 4;
        split_kernel<<<(n4 + 255) / 256, 256>>>(w2, bh, bl, n4);
        dim3 g(EMB / 128, MM / 128);
        gemm_hmma<false><<<g, 128, gemm_shm>>>(ah, al, bh, bl, b2, out,
                                               nullptr, nullptr, nullptr, nullptr, nullptr, nullptr,
                                               MM, EMB, EMB);
    }
}

// round 8
// speedup vs baseline: 1.5066x; 1.0267x over previous
#include <cuda_runtime.h>
#include <cuda_bf16.h>
#include <math.h>
#include <stdint.h>

#define BATCH 4
#define SEQ   2048
#define EMB   1024
#define NH    16
#define HD    64

// ---------------- scratch ----------------
__device__ float g_bias[65];
__device__ __nv_bfloat16 g_ah[(size_t)BATCH * SEQ * EMB];
__device__ __nv_bfloat16 g_al[(size_t)BATCH * SEQ * EMB];
__device__ __nv_bfloat16 g_bh[(size_t)3 * EMB * EMB];
__device__ __nv_bfloat16 g_bl[(size_t)3 * EMB * EMB];
#define HSZ ((size_t)BATCH * NH * SEQ * HD)
__device__ __nv_bfloat16 g_qh[HSZ], g_ql[HSZ];
__device__ __nv_bfloat16 g_kh[HSZ], g_kl[HSZ];
__device__ __nv_bfloat16 g_vh[HSZ], g_vl[HSZ];

// ---------------- PTX helpers ----------------
__device__ __forceinline__ uint32_t smem_u32(const void* p) {
    uint32_t a;
    asm("{ .reg .u64 t; cvta.to.shared.u64 t, %1; cvt.u32.u64 %0, t; }" : "=r"(a) : "l"(p));
    return a;
}
#define CP16(d, s)   asm volatile("cp.async.cg.shared.global [%0], [%1], 16;" :: "r"(d), "l"(s))
#define CP_COMMIT()  asm volatile("cp.async.commit_group;" ::: "memory")
#define CP_WAIT1()   asm volatile("cp.async.wait_group 1;" ::: "memory")
#define CP_WAIT0()   asm volatile("cp.async.wait_group 0;" ::: "memory")

#define LDSM4(r0, r1, r2, r3, a) \
    asm volatile("ldmatrix.sync.aligned.m8n8.x4.shared.b16 {%0,%1,%2,%3}, [%4];" \
        : "=r"(r0), "=r"(r1), "=r"(r2), "=r"(r3) : "r"(a))
#define LDSM4T(r0, r1, r2, r3, a) \
    asm volatile("ldmatrix.sync.aligned.m8n8.x4.trans.shared.b16 {%0,%1,%2,%3}, [%4];" \
        : "=r"(r0), "=r"(r1), "=r"(r2), "=r"(r3) : "r"(a))

#define MMA16816(d, a, b) \
    asm volatile("mma.sync.aligned.m16n8k16.row.col.f32.bf16.bf16.f32 " \
        "{%0,%1,%2,%3}, {%4,%5,%6,%7}, {%8,%9}, {%0,%1,%2,%3};" \
        : "+f"((d)[0]), "+f"((d)[1]), "+f"((d)[2]), "+f"((d)[3]) \
        : "r"((a)[0]), "r"((a)[1]), "r"((a)[2]), "r"((a)[3]), "r"((b)[0]), "r"((b)[1]))

// ---------------------------------------------------------------------------
__global__ void bias_kernel(const float* __restrict__ rel_bias) {
    int r = threadIdx.x;
    if (r < 65) {
        float s = 0.f;
        #pragma unroll
        for (int h = 0; h < NH; h++) s += rel_bias[r * NH + h];
        g_bias[r] = s * (1.0f / NH);
    }
}

// ---------------------------------------------------------------------------
__global__ __launch_bounds__(256) void split_kernel(
    const float* __restrict__ x, __nv_bfloat16* __restrict__ hi,
    __nv_bfloat16* __restrict__ lo, int n4)
{
    int i = blockIdx.x * blockDim.x + threadIdx.x;
    if (i >= n4) return;
    float4 v = ((const float4*)x)[i];
    __nv_bfloat16 h0 = __float2bfloat16(v.x), h1 = __float2bfloat16(v.y);
    __nv_bfloat16 h2 = __float2bfloat16(v.z), h3 = __float2bfloat16(v.w);
    __nv_bfloat162 H0 = {h0, h1}, H1 = {h2, h3};
    __nv_bfloat162 L0 = {__float2bfloat16(v.x - __bfloat162float(h0)),
                         __float2bfloat16(v.y - __bfloat162float(h1))};
    __nv_bfloat162 L1 = {__float2bfloat16(v.z - __bfloat162float(h2)),
                         __float2bfloat16(v.w - __bfloat162float(h3))};
    ((__nv_bfloat162*)hi)[i*2]   = H0;  ((__nv_bfloat162*)hi)[i*2+1] = H1;
    ((__nv_bfloat162*)lo)[i*2]   = L0;  ((__nv_bfloat162*)lo)[i*2+1] = L1;
}

// ---------------------------------------------------------------------------
// HMMA split-bf16 GEMM (unchanged R5/R7 config): 128x128, BK=32, 128 thr.
// ---------------------------------------------------------------------------
#define TIL 10240
#define STG (4*TIL)

template<bool QKVMODE>
__global__ __launch_bounds__(128) void gemm_hmma(
    const __nv_bfloat16* __restrict__ Ah, const __nv_bfloat16* __restrict__ Al,
    const __nv_bfloat16* __restrict__ Bh, const __nv_bfloat16* __restrict__ Bl,
    const float* __restrict__ bias, float* __restrict__ C,
    __nv_bfloat16* __restrict__ qh, __nv_bfloat16* __restrict__ ql,
    __nv_bfloat16* __restrict__ kh, __nv_bfloat16* __restrict__ kl,
    __nv_bfloat16* __restrict__ vh, __nv_bfloat16* __restrict__ vl,
    int M, int N, int K)
{
    extern __shared__ char sm[];
    uint32_t smb = smem_u32(sm);
    const int t = threadIdx.x;
    const int lane = t & 31, wid = t >> 5;
    const int wm = wid >> 1, wn = wid & 1;
    const int m0 = blockIdx.y * 128, n0 = blockIdx.x * 128;

    auto load_stage = [&](int buf, int k0) {
        uint32_t d = smb + buf * STG;
        #pragma unroll
        for (int c = 0; c < 4; c++) {
            int id = c * 128 + t;
            int row = id >> 2, ch = id & 3;
            uint32_t so = (uint32_t)(row * 80 + ch * 16);
            size_t ao = (size_t)(m0 + row) * K + k0 + ch * 8;
            size_t bo = (size_t)(n0 + row) * K + k0 + ch * 8;
            CP16(d + so,           Ah + ao);
            CP16(d + TIL + so,     Al + ao);
            CP16(d + 2*TIL + so,   Bh + bo);
            CP16(d + 3*TIL + so,   Bl + bo);
        }
    };

    float acc[4][8][4];
    #pragma unroll
    for (int i = 0; i < 4; i++)
        #pragma unroll
        for (int j = 0; j < 8; j++)
            #pragma unroll
            for (int v = 0; v < 4; v++) acc[i][j][v] = 0.f;

    const int NS = K >> 5;
    load_stage(0, 0);
    CP_COMMIT();

    for (int s = 0; s < NS; s++) {
        if (s + 1 < NS) { load_stage((s + 1) & 1, (s + 1) << 5); CP_COMMIT(); CP_WAIT1(); }
        else           { CP_WAIT0(); }
        __syncthreads();

        uint32_t abase = smb + (s & 1) * STG;
        uint32_t bbase = abase + 2 * TIL;

        #pragma unroll
        for (int ks = 0; ks < 2; ks++) {
            uint32_t a_ad[4], b_ad[4];
            #pragma unroll
            for (int mt = 0; mt < 4; mt++)
                a_ad[mt] = abase + (uint32_t)((wm*64 + mt*16 + (lane & 15)) * 80
                                              + ks*32 + (lane >> 4) * 16);
            #pragma unroll
            for (int p = 0; p < 4; p++)
                b_ad[p] = bbase + (uint32_t)((wn*64 + p*16 + (lane >> 4) * 8 + (lane & 7)) * 80
                                             + ks*32 + ((lane >> 3) & 1) * 16);

            uint32_t af[4][4], xf[4][4], bf[8][2];
            #pragma unroll
            for (int mt = 0; mt < 4; mt++)
                LDSM4(af[mt][0], af[mt][1], af[mt][2], af[mt][3], a_ad[mt]);
            #pragma unroll
            for (int p = 0; p < 4; p++)
                LDSM4(bf[2*p][0], bf[2*p][1], bf[2*p+1][0], bf[2*p+1][1], b_ad[p]);
            #pragma unroll
            for (int mt = 0; mt < 4; mt++)
                #pragma unroll
                for (int j = 0; j < 8; j++) MMA16816(acc[mt][j], af[mt], bf[j]);
            #pragma unroll
            for (int mt = 0; mt < 4; mt++)
                LDSM4(xf[mt][0], xf[mt][1], xf[mt][2], xf[mt][3], a_ad[mt] + TIL);
            #pragma unroll
            for (int mt = 0; mt < 4; mt++)
                #pragma unroll
                for (int j = 0; j < 8; j++) MMA16816(acc[mt][j], xf[mt], bf[j]);
            #pragma unroll
            for (int p = 0; p < 4; p++)
                LDSM4(bf[2*p][0], bf[2*p][1], bf[2*p+1][0], bf[2*p+1][1], b_ad[p] + TIL);
            #pragma unroll
            for (int mt = 0; mt < 4; mt++)
                #pragma unroll
                for (int j = 0; j < 8; j++) MMA16816(acc[mt][j], af[mt], bf[j]);
        }
        __syncthreads();
    }

    #pragma unroll
    for (int mt = 0; mt < 4; mt++) {
        int m = m0 + wm*64 + mt*16 + (lane >> 2);
        #pragma unroll
        for (int j = 0; j < 8; j++) {
            int n = n0 + wn*64 + j*8 + (lane & 3) * 2;
            float b0 = bias[n], b1 = bias[n + 1];
            if (!QKVMODE) {
                *(float2*)(&C[(size_t)m * N + n]) =
                    make_float2(acc[mt][j][0] + b0, acc[mt][j][1] + b1);
                *(float2*)(&C[(size_t)(m + 8) * N + n]) =
                    make_float2(acc[mt][j][2] + b0, acc[mt][j][3] + b1);
            } else {
                int which = n >> 10;
                int hh = (n >> 6) & 15;
                int d = n & 63;
                __nv_bfloat16 *ph, *pl;
                float sc = 1.0f;
                if (which == 0)      { ph = qh; pl = ql; sc = 0.125f; }
                else if (which == 1) { ph = kh; pl = kl; }
                else                 { ph = vh; pl = vl; }
                #pragma unroll
                for (int r = 0; r < 2; r++) {
                    int mm = m + r * 8;
                    float v0 = (acc[mt][j][2*r]   + b0) * sc;
                    float v1 = (acc[mt][j][2*r+1] + b1) * sc;
                    size_t o = (((size_t)(mm >> 11) * NH + hh) * SEQ + (mm & 2047)) * HD + d;
                    __nv_bfloat16 h0 = __float2bfloat16(v0);
                    __nv_bfloat16 h1 = __float2bfloat16(v1);
                    __nv_bfloat162 H = {h0, h1};
                    __nv_bfloat162 L = {__float2bfloat16(v0 - __bfloat162float(h0)),
                                        __float2bfloat16(v1 - __bfloat162float(h1))};
                    *(__nv_bfloat162*)(ph + o) = H;
                    *(__nv_bfloat162*)(pl + o) = L;
                }
            }
        }
    }
}

// ---------------------------------------------------------------------------
// HMMA flash attention: 256 threads (8 warps x m16), KV tile **128**,
// 2-stage cp.async, fused ctx-split epilogue.
// ---------------------------------------------------------------------------
#define AQH 0u
#define AQL 18432u
#define AST 36864u
#define ASS 73728u          // stage: Kh,Kl,Vh,Vl @ 18432 each
#define AKL 18432u
#define AVH 36864u
#define AVL 55296u
#define ALUT 184320u
#define ASMEM 184640u

__device__ __forceinline__ uint32_t packres(float a, float b, float& ra, float& rb) {
    __nv_bfloat162 h;
    h.x = __float2bfloat16(a); h.y = __float2bfloat16(b);
    ra = a - __bfloat162float(h.x);
    rb = b - __bfloat162float(h.y);
    return *(uint32_t*)&h;
}
__device__ __forceinline__ uint32_t packbf(float a, float b) {
    __nv_bfloat162 h;
    h.x = __float2bfloat16(a); h.y = __float2bfloat16(b);
    return *(uint32_t*)&h;
}

__global__ __launch_bounds__(256) void attn_hmma(
    const __nv_bfloat16* __restrict__ qh_g, const __nv_bfloat16* __restrict__ ql_g,
    const __nv_bfloat16* __restrict__ kh_g, const __nv_bfloat16* __restrict__ kl_g,
    const __nv_bfloat16* __restrict__ vh_g, const __nv_bfloat16* __restrict__ vl_g,
    __nv_bfloat16* __restrict__ ch_g, __nv_bfloat16* __restrict__ cl_g)
{
    extern __shared__ char sm[];
    uint32_t smb = smem_u32(sm);
    const int t = threadIdx.x, lane = t & 31, wq = t >> 5;
    const int q0 = blockIdx.x * 128, h = blockIdx.y, b = blockIdx.z;

    float* lut = (float*)(sm + ALUT);
    if (t < 65) lut[t] = g_bias[t];

    const size_t hb = ((size_t)b * NH + h) * SEQ;
    const size_t qg = (hb + q0) * HD;

    // Q: 2 arrays x 1024 16B chunks
    #pragma unroll
    for (int i = 0; i < 4; i++) {
        int id = t * 4 + i, row = id >> 3, ch = id & 7;
        uint32_t so = (uint32_t)(row * 144 + ch * 16);
        size_t go = qg + (size_t)row * 64 + ch * 8;
        CP16(smb + AQH + so, qh_g + go);
        CP16(smb + AQL + so, ql_g + go);
    }
    // KV stage: 128 rows per array -> 1024 chunks/array, 4 per thread
    auto load_kv = [&](int buf, int j0) {
        uint32_t sb = smb + AST + (uint32_t)buf * ASS;
        size_t gb = (hb + j0) * HD;
        #pragma unroll
        for (int c = 0; c < 4; c++) {
            int id = c * 256 + t, row = id >> 3, ch = id & 7;
            uint32_t so = (uint32_t)(row * 144 + ch * 16);
            size_t go = gb + (size_t)row * 64 + ch * 8;
            CP16(sb + so,       kh_g + go);
            CP16(sb + AKL + so, kl_g + go);
            CP16(sb + AVH + so, vh_g + go);
            CP16(sb + AVL + so, vl_g + go);
        }
    };
    load_kv(0, 0);
    CP_COMMIT();

    uint32_t qhf[4][4], qlf[4][4];
    float oacc[8][4];
    #pragma unroll
    for (int i = 0; i < 8; i++)
        #pragma unroll
        for (int j = 0; j < 4; j++) oacc[i][j] = 0.f;
    float mrow0 = -1e30f, mrow1 = -1e30f, lrow0 = 0.f, lrow1 = 0.f;

    const int qr0 = q0 + wq * 16 + (lane >> 2);
    const int NT = SEQ / 128;

    for (int jt = 0; jt < NT; jt++) {
        if (jt + 1 < NT) { load_kv((jt + 1) & 1, (jt + 1) * 128); CP_COMMIT(); CP_WAIT1(); }
        else            { CP_WAIT0(); }
        __syncthreads();

        if (jt == 0) {
            #pragma unroll
            for (int ks = 0; ks < 4; ks++) {
                uint32_t ar = (uint32_t)((wq*16 + ((lane>>3)&1)*8 + (lane&7)) * 144
                                         + ks*32 + ((lane>>4)&1)*16);
                LDSM4(qhf[ks][0], qhf[ks][1], qhf[ks][2], qhf[ks][3], smb + AQH + ar);
                LDSM4(qlf[ks][0], qlf[ks][1], qlf[ks][2], qlf[ks][3], smb + AQL + ar);
            }
        }

        uint32_t sb = smb + AST + (uint32_t)(jt & 1) * ASS;
        float sacc[16][4];
        #pragma unroll
        for (int i = 0; i < 16; i++)
            #pragma unroll
            for (int j = 0; j < 4; j++) sacc[i][j] = 0.f;

        // S = Qh*Kh + Ql*Kh + Qh*Kl   (p over 8 k-subtiles of 16)
        #pragma unroll
        for (int ks = 0; ks < 4; ks++) {
            #pragma unroll
            for (int p = 0; p < 8; p++) {
                uint32_t kr = (uint32_t)((p*16 + ((lane>>4)&1)*8 + (lane&7)) * 144
                                         + ks*32 + ((lane>>3)&1)*16);
                uint32_t h0, h1, h2, h3, l0, l1, l2, l3;
                LDSM4(h0, h1, h2, h3, sb + kr);
                LDSM4(l0, l1, l2, l3, sb + AKL + kr);
                uint32_t bh0[2] = {h0, h1}, bh1[2] = {h2, h3};
                uint32_t bl0[2] = {l0, l1}, bl1[2] = {l2, l3};
                MMA16816(sacc[2*p],   qhf[ks], bh0);
                MMA16816(sacc[2*p],   qlf[ks], bh0);
                MMA16816(sacc[2*p],   qhf[ks], bl0);
                MMA16816(sacc[2*p+1], qhf[ks], bh1);
                MMA16816(sacc[2*p+1], qlf[ks], bh1);
                MMA16816(sacc[2*p+1], qhf[ks], bl1);
            }
        }

        // bias + online softmax
        float mx0 = -1e30f, mx1 = -1e30f;
        #pragma unroll
        for (int nt = 0; nt < 16; nt++) {
            #pragma unroll
            for (int j = 0; j < 2; j++) {
                int k = jt * 128 + nt * 8 + (lane & 3) * 2 + j;
                int r = qr0 - k;
                int r0 = r < -32 ? -32 : (r > 32 ? 32 : r);
                int r1 = (r + 8) < -32 ? -32 : ((r + 8) > 32 ? 32 : (r + 8));
                sacc[nt][j]     += lut[r0 + 32];
                sacc[nt][2 + j] += lut[r1 + 32];
                mx0 = fmaxf(mx0, sacc[nt][j]);
                mx1 = fmaxf(mx1, sacc[nt][2 + j]);
            }
        }
        #pragma unroll
        for (int off = 1; off <= 2; off <<= 1) {
            mx0 = fmaxf(mx0, __shfl_xor_sync(0xffffffffu, mx0, off));
            mx1 = fmaxf(mx1, __shfl_xor_sync(0xffffffffu, mx1, off));
        }
        float mn0 = fmaxf(mrow0, mx0), mn1 = fmaxf(mrow1, mx1);
        float al0 = __expf(mrow0 - mn0), al1 = __expf(mrow1 - mn1);
        mrow0 = mn0; mrow1 = mn1;
        float s0 = 0.f, s1 = 0.f;
        #pragma unroll
        for (int nt = 0; nt < 16; nt++) {
            #pragma unroll
            for (int j = 0; j < 2; j++) {
                float p0 = __expf(sacc[nt][j] - mn0);
                float p1 = __expf(sacc[nt][2 + j] - mn1);
                sacc[nt][j] = p0;  sacc[nt][2 + j] = p1;
                s0 += p0;  s1 += p1;
            }
        }
        #pragma unroll
        for (int off = 1; off <= 2; off <<= 1) {
            s0 += __shfl_xor_sync(0xffffffffu, s0, off);
            s1 += __shfl_xor_sync(0xffffffffu, s1, off);
        }
        lrow0 = lrow0 * al0 + s0;
        lrow1 = lrow1 * al1 + s1;
        #pragma unroll
        for (int nt = 0; nt < 8; nt++) {
            oacc[nt][0] *= al0;  oacc[nt][1] *= al0;
            oacc[nt][2] *= al1;  oacc[nt][3] *= al1;
        }

        // O += Ph*Vh + Pl*Vh + Ph*Vl   (ks over 8 k-subtiles of 16)
        #pragma unroll
        for (int ks = 0; ks < 8; ks++) {
            uint32_t ph[4], pl[4];
            float ra, rb;
            ph[0] = packres(sacc[2*ks][0],   sacc[2*ks][1],   ra, rb); pl[0] = packbf(ra, rb);
            ph[1] = packres(sacc[2*ks][2],   sacc[2*ks][3],   ra, rb); pl[1] = packbf(ra, rb);
            ph[2] = packres(sacc[2*ks+1][0], sacc[2*ks+1][1], ra, rb); pl[2] = packbf(ra, rb);
            ph[3] = packres(sacc[2*ks+1][2], sacc[2*ks+1][3], ra, rb); pl[3] = packbf(ra, rb);
            #pragma unroll
            for (int p = 0; p < 4; p++) {
                uint32_t vr = (uint32_t)((ks*16 + ((lane>>3)&1)*8 + (lane&7)) * 144
                                         + p*32 + ((lane>>4)&1)*16);
                uint32_t h0, h1, h2, h3, l0, l1, l2, l3;
                LDSM4T(h0, h1, h2, h3, sb + AVH + vr);
                LDSM4T(l0, l1, l2, l3, sb + AVL + vr);
                uint32_t bh0[2] = {h0, h1}, bh1[2] = {h2, h3};
                uint32_t bl0[2] = {l0, l1}, bl1[2] = {l2, l3};
                MMA16816(oacc[2*p],   ph, bh0);
                MMA16816(oacc[2*p],   pl, bh0);
                MMA16816(oacc[2*p],   ph, bl0);
                MMA16816(oacc[2*p+1], ph, bh1);
                MMA16816(oacc[2*p+1], pl, bh1);
                MMA16816(oacc[2*p+1], ph, bl1);
            }
        }
        __syncthreads();
    }

    // fused ctx-split epilogue
    float inv0 = 1.0f / lrow0, inv1 = 1.0f / lrow1;
    size_t row0 = ((size_t)b * SEQ + qr0) * EMB + h * HD;
    #pragma unroll
    for (int nt = 0; nt < 8; nt++) {
        int d = nt * 8 + (lane & 3) * 2;
        float v0 = oacc[nt][0] * inv0, v1 = oacc[nt][1] * inv0;
        float v2 = oacc[nt][2] * inv1, v3 = oacc[nt][3] * inv1;
        float ra, rb;
        uint32_t H0 = packres(v0, v1, ra, rb), L0 = packbf(ra, rb);
        *(uint32_t*)(ch_g + row0 + d) = H0;
        *(uint32_t*)(cl_g + row0 + d) = L0;
        uint32_t H1 = packres(v2, v3, ra, rb), L1 = packbf(ra, rb);
        *(uint32_t*)(ch_g + row0 + (size_t)8 * EMB + d) = H1;
        *(uint32_t*)(cl_g + row0 + (size_t)8 * EMB + d) = L1;
    }
}

// ---------------------------------------------------------------------------
extern "C" void kernel_launch(void* const* d_in, const int* in_sizes, int n_in,
                              void* d_out, int out_size)
{
    const float* x  = (const float*)d_in[0];
    const float* w1 = (const float*)d_in[1];
    const float* b1 = (const float*)d_in[2];
    const float* w2 = (const float*)d_in[3];
    const float* b2 = (const float*)d_in[4];
    const float* rb = (const float*)d_in[5];
    float* out = (float*)d_out;

    __nv_bfloat16 *ah, *al, *bh, *bl, *qh, *ql, *kh, *kl, *vh, *vl;
    cudaGetSymbolAddress((void**)&ah, g_ah);
    cudaGetSymbolAddress((void**)&al, g_al);
    cudaGetSymbolAddress((void**)&bh, g_bh);
    cudaGetSymbolAddress((void**)&bl, g_bl);
    cudaGetSymbolAddress((void**)&qh, g_qh);
    cudaGetSymbolAddress((void**)&ql, g_ql);
    cudaGetSymbolAddress((void**)&kh, g_kh);
    cudaGetSymbolAddress((void**)&kl, g_kl);
    cudaGetSymbolAddress((void**)&vh, g_vh);
    cudaGetSymbolAddress((void**)&vl, g_vl);

    const int MM = BATCH * SEQ;
    const size_t gemm_shm = 2 * (size_t)STG;   // 81920 B
    cudaFuncSetAttribute(gemm_hmma<true>,  cudaFuncAttributeMaxDynamicSharedMemorySize, (int)gemm_shm);
    cudaFuncSetAttribute(gemm_hmma<false>, cudaFuncAttributeMaxDynamicSharedMemorySize, (int)gemm_shm);
    cudaFuncSetAttribute(attn_hmma, cudaFuncAttributeMaxDynamicSharedMemorySize, (int)ASMEM);

    bias_kernel<<<1, 96>>>(rb);

    {   // split x, w1
        int n4 = MM * EMB / 4;
        split_kernel<<<(n4 + 255) / 256, 256>>>(x, ah, al, n4);
        n4 = 3 * EMB * EMB / 4;
        split_kernel<<<(n4 + 255) / 256, 256>>>(w1, bh, bl, n4);
    }
    {   // QKV projection with fused per-head split epilogue
        dim3 g(3 * EMB / 128, MM / 128);
        gemm_hmma<true><<<g, 128, gemm_shm>>>(ah, al, bh, bl, b1, nullptr,
                                              qh, ql, kh, kl, vh, vl,
                                              MM, 3 * EMB, EMB);
    }
    {   // attention with fused ctx-split epilogue (writes ah/al)
        dim3 g(SEQ / 128, NH, BATCH);
        attn_hmma<<<g, 256, ASMEM>>>(qh, ql, kh, kl, vh, vl, ah, al);
    }
    {   // split w2; out projection
        int n4 = EMB * EMB / 4;
        split_kernel<<<(n4 + 255) / 256, 256>>>(w2, bh, bl, n4);
        dim3 g(EMB / 128, MM / 128);
        gemm_hmma<false><<<g, 128, gemm_shm>>>(ah, al, bh, bl, b2, out,
                                               nullptr, nullptr, nullptr, nullptr, nullptr, nullptr,
                                               MM, EMB, EMB);
    }
}

// round 9
// speedup vs baseline: 1.5366x; 1.0199x over previous
#include <cuda_runtime.h>
#include <cuda_bf16.h>
#include <math.h>
#include <stdint.h>

#define BATCH 4
#define SEQ   2048
#define EMB   1024
#define NH    16
#define HD    64

// ---------------- scratch ----------------
__device__ float g_bias[65];
__device__ __nv_bfloat16 g_ah[(size_t)BATCH * SEQ * EMB];
__device__ __nv_bfloat16 g_al[(size_t)BATCH * SEQ * EMB];
__device__ __nv_bfloat16 g_bh[(size_t)3 * EMB * EMB];
__device__ __nv_bfloat16 g_bl[(size_t)3 * EMB * EMB];
#define HSZ ((size_t)BATCH * NH * SEQ * HD)
__device__ __nv_bfloat16 g_qh[HSZ], g_ql[HSZ];
__device__ __nv_bfloat16 g_kh[HSZ], g_kl[HSZ];
__device__ __nv_bfloat16 g_vh[HSZ], g_vl[HSZ];

// ---------------- PTX helpers ----------------
__device__ __forceinline__ uint32_t smem_u32(const void* p) {
    uint32_t a;
    asm("{ .reg .u64 t; cvta.to.shared.u64 t, %1; cvt.u32.u64 %0, t; }" : "=r"(a) : "l"(p));
    return a;
}
#define CP16(d, s)   asm volatile("cp.async.cg.shared.global [%0], [%1], 16;" :: "r"(d), "l"(s))
#define CP_COMMIT()  asm volatile("cp.async.commit_group;" ::: "memory")
#define CP_WAIT1()   asm volatile("cp.async.wait_group 1;" ::: "memory")
#define CP_WAIT0()   asm volatile("cp.async.wait_group 0;" ::: "memory")

#define LDSM4(r0, r1, r2, r3, a) \
    asm volatile("ldmatrix.sync.aligned.m8n8.x4.shared.b16 {%0,%1,%2,%3}, [%4];" \
        : "=r"(r0), "=r"(r1), "=r"(r2), "=r"(r3) : "r"(a))
#define LDSM4T(r0, r1, r2, r3, a) \
    asm volatile("ldmatrix.sync.aligned.m8n8.x4.trans.shared.b16 {%0,%1,%2,%3}, [%4];" \
        : "=r"(r0), "=r"(r1), "=r"(r2), "=r"(r3) : "r"(a))

#define MMA16816(d, a, b) \
    asm volatile("mma.sync.aligned.m16n8k16.row.col.f32.bf16.bf16.f32 " \
        "{%0,%1,%2,%3}, {%4,%5,%6,%7}, {%8,%9}, {%0,%1,%2,%3};" \
        : "+f"((d)[0]), "+f"((d)[1]), "+f"((d)[2]), "+f"((d)[3]) \
        : "r"((a)[0]), "r"((a)[1]), "r"((a)[2]), "r"((a)[3]), "r"((b)[0]), "r"((b)[1]))

// ---------------------------------------------------------------------------
__global__ void bias_kernel(const float* __restrict__ rel_bias) {
    int r = threadIdx.x;
    if (r < 65) {
        float s = 0.f;
        #pragma unroll
        for (int h = 0; h < NH; h++) s += rel_bias[r * NH + h];
        g_bias[r] = s * (1.0f / NH);
    }
}

// ---------------------------------------------------------------------------
__global__ __launch_bounds__(256) void split_kernel(
    const float* __restrict__ x, __nv_bfloat16* __restrict__ hi,
    __nv_bfloat16* __restrict__ lo, int n4)
{
    int i = blockIdx.x * blockDim.x + threadIdx.x;
    if (i >= n4) return;
    float4 v = ((const float4*)x)[i];
    __nv_bfloat16 h0 = __float2bfloat16(v.x), h1 = __float2bfloat16(v.y);
    __nv_bfloat16 h2 = __float2bfloat16(v.z), h3 = __float2bfloat16(v.w);
    __nv_bfloat162 H0 = {h0, h1}, H1 = {h2, h3};
    __nv_bfloat162 L0 = {__float2bfloat16(v.x - __bfloat162float(h0)),
                         __float2bfloat16(v.y - __bfloat162float(h1))};
    __nv_bfloat162 L1 = {__float2bfloat16(v.z - __bfloat162float(h2)),
                         __float2bfloat16(v.w - __bfloat162float(h3))};
    ((__nv_bfloat162*)hi)[i*2]   = H0;  ((__nv_bfloat162*)hi)[i*2+1] = H1;
    ((__nv_bfloat162*)lo)[i*2]   = L0;  ((__nv_bfloat162*)lo)[i*2+1] = L1;
}

// ---------------------------------------------------------------------------
// HMMA split-bf16 GEMM: 128x128, BK=32, 128 thr, 2x2 warp grid.
// B-fragments streamed per 16-row subtile (8 live regs) to kill spills.
// ---------------------------------------------------------------------------
#define TIL 10240
#define STG (4*TIL)

template<bool QKVMODE>
__global__ __launch_bounds__(128) void gemm_hmma(
    const __nv_bfloat16* __restrict__ Ah, const __nv_bfloat16* __restrict__ Al,
    const __nv_bfloat16* __restrict__ Bh, const __nv_bfloat16* __restrict__ Bl,
    const float* __restrict__ bias, float* __restrict__ C,
    __nv_bfloat16* __restrict__ qh, __nv_bfloat16* __restrict__ ql,
    __nv_bfloat16* __restrict__ kh, __nv_bfloat16* __restrict__ kl,
    __nv_bfloat16* __restrict__ vh, __nv_bfloat16* __restrict__ vl,
    int M, int N, int K)
{
    extern __shared__ char sm[];
    uint32_t smb = smem_u32(sm);
    const int t = threadIdx.x;
    const int lane = t & 31, wid = t >> 5;
    const int wm = wid >> 1, wn = wid & 1;
    const int m0 = blockIdx.y * 128, n0 = blockIdx.x * 128;

    auto load_stage = [&](int buf, int k0) {
        uint32_t d = smb + buf * STG;
        #pragma unroll
        for (int c = 0; c < 4; c++) {
            int id = c * 128 + t;
            int row = id >> 2, ch = id & 3;
            uint32_t so = (uint32_t)(row * 80 + ch * 16);
            size_t ao = (size_t)(m0 + row) * K + k0 + ch * 8;
            size_t bo = (size_t)(n0 + row) * K + k0 + ch * 8;
            CP16(d + so,           Ah + ao);
            CP16(d + TIL + so,     Al + ao);
            CP16(d + 2*TIL + so,   Bh + bo);
            CP16(d + 3*TIL + so,   Bl + bo);
        }
    };

    float acc[4][8][4];
    #pragma unroll
    for (int i = 0; i < 4; i++)
        #pragma unroll
        for (int j = 0; j < 8; j++)
            #pragma unroll
            for (int v = 0; v < 4; v++) acc[i][j][v] = 0.f;

    const int NS = K >> 5;
    load_stage(0, 0);
    CP_COMMIT();

    for (int s = 0; s < NS; s++) {
        if (s + 1 < NS) { load_stage((s + 1) & 1, (s + 1) << 5); CP_COMMIT(); CP_WAIT1(); }
        else           { CP_WAIT0(); }
        __syncthreads();

        uint32_t abase = smb + (s & 1) * STG;
        uint32_t bbase = abase + 2 * TIL;

        #pragma unroll
        for (int ks = 0; ks < 2; ks++) {
            // A hi + lo fragments for this k-chunk (32 regs live)
            uint32_t af[4][4], xf[4][4];
            #pragma unroll
            for (int mt = 0; mt < 4; mt++) {
                uint32_t a_ad = abase + (uint32_t)((wm*64 + mt*16 + (lane & 15)) * 80
                                                   + ks*32 + (lane >> 4) * 16);
                LDSM4(af[mt][0], af[mt][1], af[mt][2], af[mt][3], a_ad);
                LDSM4(xf[mt][0], xf[mt][1], xf[mt][2], xf[mt][3], a_ad + TIL);
            }
            // stream B per 16-row subtile: only 8 B-frag regs live
            #pragma unroll
            for (int p = 0; p < 4; p++) {
                uint32_t b_ad = bbase + (uint32_t)((wn*64 + p*16 + (lane >> 4) * 8 + (lane & 7)) * 80
                                                   + ks*32 + ((lane >> 3) & 1) * 16);
                uint32_t bh0, bh1, bh2, bh3;
                LDSM4(bh0, bh1, bh2, bh3, b_ad);
                uint32_t bfh0[2] = {bh0, bh1}, bfh1[2] = {bh2, bh3};
                #pragma unroll
                for (int mt = 0; mt < 4; mt++) {
                    MMA16816(acc[mt][2*p],   af[mt], bfh0);
                    MMA16816(acc[mt][2*p+1], af[mt], bfh1);
                }
                #pragma unroll
                for (int mt = 0; mt < 4; mt++) {
                    MMA16816(acc[mt][2*p],   xf[mt], bfh0);
                    MMA16816(acc[mt][2*p+1], xf[mt], bfh1);
                }
                uint32_t bl0, bl1, bl2, bl3;
                LDSM4(bl0, bl1, bl2, bl3, b_ad + TIL);
                uint32_t bfl0[2] = {bl0, bl1}, bfl1[2] = {bl2, bl3};
                #pragma unroll
                for (int mt = 0; mt < 4; mt++) {
                    MMA16816(acc[mt][2*p],   af[mt], bfl0);
                    MMA16816(acc[mt][2*p+1], af[mt], bfl1);
                }
            }
        }
        __syncthreads();
    }

    #pragma unroll
    for (int mt = 0; mt < 4; mt++) {
        int m = m0 + wm*64 + mt*16 + (lane >> 2);
        #pragma unroll
        for (int j = 0; j < 8; j++) {
            int n = n0 + wn*64 + j*8 + (lane & 3) * 2;
            float b0 = bias[n], b1 = bias[n + 1];
            if (!QKVMODE) {
                *(float2*)(&C[(size_t)m * N + n]) =
                    make_float2(acc[mt][j][0] + b0, acc[mt][j][1] + b1);
                *(float2*)(&C[(size_t)(m + 8) * N + n]) =
                    make_float2(acc[mt][j][2] + b0, acc[mt][j][3] + b1);
            } else {
                int which = n >> 10;
                int hh = (n >> 6) & 15;
                int d = n & 63;
                __nv_bfloat16 *ph, *pl;
                float sc = 1.0f;
                if (which == 0)      { ph = qh; pl = ql; sc = 0.125f; }
                else if (which == 1) { ph = kh; pl = kl; }
                else                 { ph = vh; pl = vl; }
                #pragma unroll
                for (int r = 0; r < 2; r++) {
                    int mm = m + r * 8;
                    float v0 = (acc[mt][j][2*r]   + b0) * sc;
                    float v1 = (acc[mt][j][2*r+1] + b1) * sc;
                    size_t o = (((size_t)(mm >> 11) * NH + hh) * SEQ + (mm & 2047)) * HD + d;
                    __nv_bfloat16 h0 = __float2bfloat16(v0);
                    __nv_bfloat16 h1 = __float2bfloat16(v1);
                    __nv_bfloat162 H = {h0, h1};
                    __nv_bfloat162 L = {__float2bfloat16(v0 - __bfloat162float(h0)),
                                        __float2bfloat16(v1 - __bfloat162float(h1))};
                    *(__nv_bfloat162*)(ph + o) = H;
                    *(__nv_bfloat162*)(pl + o) = L;
                }
            }
        }
    }
}

// ---------------------------------------------------------------------------
// HMMA flash attention (R8 config): 256 threads, KV tile 128, fused epilogue.
// ---------------------------------------------------------------------------
#define AQH 0u
#define AQL 18432u
#define AST 36864u
#define ASS 73728u
#define AKL 18432u
#define AVH 36864u
#define AVL 55296u
#define ALUT 184320u
#define ASMEM 184640u

__device__ __forceinline__ uint32_t packres(float a, float b, float& ra, float& rb) {
    __nv_bfloat162 h;
    h.x = __float2bfloat16(a); h.y = __float2bfloat16(b);
    ra = a - __bfloat162float(h.x);
    rb = b - __bfloat162float(h.y);
    return *(uint32_t*)&h;
}
__device__ __forceinline__ uint32_t packbf(float a, float b) {
    __nv_bfloat162 h;
    h.x = __float2bfloat16(a); h.y = __float2bfloat16(b);
    return *(uint32_t*)&h;
}

__global__ __launch_bounds__(256) void attn_hmma(
    const __nv_bfloat16* __restrict__ qh_g, const __nv_bfloat16* __restrict__ ql_g,
    const __nv_bfloat16* __restrict__ kh_g, const __nv_bfloat16* __restrict__ kl_g,
    const __nv_bfloat16* __restrict__ vh_g, const __nv_bfloat16* __restrict__ vl_g,
    __nv_bfloat16* __restrict__ ch_g, __nv_bfloat16* __restrict__ cl_g)
{
    extern __shared__ char sm[];
    uint32_t smb = smem_u32(sm);
    const int t = threadIdx.x, lane = t & 31, wq = t >> 5;
    const int q0 = blockIdx.x * 128, h = blockIdx.y, b = blockIdx.z;

    float* lut = (float*)(sm + ALUT);
    if (t < 65) lut[t] = g_bias[t];

    const size_t hb = ((size_t)b * NH + h) * SEQ;
    const size_t qg = (hb + q0) * HD;

    #pragma unroll
    for (int i = 0; i < 4; i++) {
        int id = t * 4 + i, row = id >> 3, ch = id & 7;
        uint32_t so = (uint32_t)(row * 144 + ch * 16);
        size_t go = qg + (size_t)row * 64 + ch * 8;
        CP16(smb + AQH + so, qh_g + go);
        CP16(smb + AQL + so, ql_g + go);
    }
    auto load_kv = [&](int buf, int j0) {
        uint32_t sb = smb + AST + (uint32_t)buf * ASS;
        size_t gb = (hb + j0) * HD;
        #pragma unroll
        for (int c = 0; c < 4; c++) {
            int id = c * 256 + t, row = id >> 3, ch = id & 7;
            uint32_t so = (uint32_t)(row * 144 + ch * 16);
            size_t go = gb + (size_t)row * 64 + ch * 8;
            CP16(sb + so,       kh_g + go);
            CP16(sb + AKL + so, kl_g + go);
            CP16(sb + AVH + so, vh_g + go);
            CP16(sb + AVL + so, vl_g + go);
        }
    };
    load_kv(0, 0);
    CP_COMMIT();

    uint32_t qhf[4][4], qlf[4][4];
    float oacc[8][4];
    #pragma unroll
    for (int i = 0; i < 8; i++)
        #pragma unroll
        for (int j = 0; j < 4; j++) oacc[i][j] = 0.f;
    float mrow0 = -1e30f, mrow1 = -1e30f, lrow0 = 0.f, lrow1 = 0.f;

    const int qr0 = q0 + wq * 16 + (lane >> 2);
    const int NT = SEQ / 128;

    for (int jt = 0; jt < NT; jt++) {
        if (jt + 1 < NT) { load_kv((jt + 1) & 1, (jt + 1) * 128); CP_COMMIT(); CP_WAIT1(); }
        else            { CP_WAIT0(); }
        __syncthreads();

        if (jt == 0) {
            #pragma unroll
            for (int ks = 0; ks < 4; ks++) {
                uint32_t ar = (uint32_t)((wq*16 + ((lane>>3)&1)*8 + (lane&7)) * 144
                                         + ks*32 + ((lane>>4)&1)*16);
                LDSM4(qhf[ks][0], qhf[ks][1], qhf[ks][2], qhf[ks][3], smb + AQH + ar);
                LDSM4(qlf[ks][0], qlf[ks][1], qlf[ks][2], qlf[ks][3], smb + AQL + ar);
            }
        }

        uint32_t sb = smb + AST + (uint32_t)(jt & 1) * ASS;
        float sacc[16][4];
        #pragma unroll
        for (int i = 0; i < 16; i++)
            #pragma unroll
            for (int j = 0; j < 4; j++) sacc[i][j] = 0.f;

        #pragma unroll
        for (int ks = 0; ks < 4; ks++) {
            #pragma unroll
            for (int p = 0; p < 8; p++) {
                uint32_t kr = (uint32_t)((p*16 + ((lane>>4)&1)*8 + (lane&7)) * 144
                                         + ks*32 + ((lane>>3)&1)*16);
                uint32_t h0, h1, h2, h3, l0, l1, l2, l3;
                LDSM4(h0, h1, h2, h3, sb + kr);
                LDSM4(l0, l1, l2, l3, sb + AKL + kr);
                uint32_t bh0[2] = {h0, h1}, bh1[2] = {h2, h3};
                uint32_t bl0[2] = {l0, l1}, bl1[2] = {l2, l3};
                MMA16816(sacc[2*p],   qhf[ks], bh0);
                MMA16816(sacc[2*p],   qlf[ks], bh0);
                MMA16816(sacc[2*p],   qhf[ks], bl0);
                MMA16816(sacc[2*p+1], qhf[ks], bh1);
                MMA16816(sacc[2*p+1], qlf[ks], bh1);
                MMA16816(sacc[2*p+1], qhf[ks], bl1);
            }
        }

        float mx0 = -1e30f, mx1 = -1e30f;
        #pragma unroll
        for (int nt = 0; nt < 16; nt++) {
            #pragma unroll
            for (int j = 0; j < 2; j++) {
                int k = jt * 128 + nt * 8 + (lane & 3) * 2 + j;
                int r = qr0 - k;
                int r0 = r < -32 ? -32 : (r > 32 ? 32 : r);
                int r1 = (r + 8) < -32 ? -32 : ((r + 8) > 32 ? 32 : (r + 8));
                sacc[nt][j]     += lut[r0 + 32];
                sacc[nt][2 + j] += lut[r1 + 32];
                mx0 = fmaxf(mx0, sacc[nt][j]);
                mx1 = fmaxf(mx1, sacc[nt][2 + j]);
            }
        }
        #pragma unroll
        for (int off = 1; off <= 2; off <<= 1) {
            mx0 = fmaxf(mx0, __shfl_xor_sync(0xffffffffu, mx0, off));
            mx1 = fmaxf(mx1, __shfl_xor_sync(0xffffffffu, mx1, off));
        }
        float mn0 = fmaxf(mrow0, mx0), mn1 = fmaxf(mrow1, mx1);
        float al0 = __expf(mrow0 - mn0), al1 = __expf(mrow1 - mn1);
        mrow0 = mn0; mrow1 = mn1;
        float s0 = 0.f, s1 = 0.f;
        #pragma unroll
        for (int nt = 0; nt < 16; nt++) {
            #pragma unroll
            for (int j = 0; j < 2; j++) {
                float p0 = __expf(sacc[nt][j] - mn0);
                float p1 = __expf(sacc[nt][2 + j] - mn1);
                sacc[nt][j] = p0;  sacc[nt][2 + j] = p1;
                s0 += p0;  s1 += p1;
            }
        }
        #pragma unroll
        for (int off = 1; off <= 2; off <<= 1) {
            s0 += __shfl_xor_sync(0xffffffffu, s0, off);
            s1 += __shfl_xor_sync(0xffffffffu, s1, off);
        }
        lrow0 = lrow0 * al0 + s0;
        lrow1 = lrow1 * al1 + s1;
        #pragma unroll
        for (int nt = 0; nt < 8; nt++) {
            oacc[nt][0] *= al0;  oacc[nt][1] *= al0;
            oacc[nt][2] *= al1;  oacc[nt][3] *= al1;
        }

        #pragma unroll
        for (int ks = 0; ks < 8; ks++) {
            uint32_t ph[4], pl[4];
            float ra, rb;
            ph[0] = packres(sacc[2*ks][0],   sacc[2*ks][1],   ra, rb); pl[0] = packbf(ra, rb);
            ph[1] = packres(sacc[2*ks][2],   sacc[2*ks][3],   ra, rb); pl[1] = packbf(ra, rb);
            ph[2] = packres(sacc[2*ks+1][0], sacc[2*ks+1][1], ra, rb); pl[2] = packbf(ra, rb);
            ph[3] = packres(sacc[2*ks+1][2], sacc[2*ks+1][3], ra, rb); pl[3] = packbf(ra, rb);
            #pragma unroll
            for (int p = 0; p < 4; p++) {
                uint32_t vr = (uint32_t)((ks*16 + ((lane>>3)&1)*8 + (lane&7)) * 144
                                         + p*32 + ((lane>>4)&1)*16);
                uint32_t h0, h1, h2, h3, l0, l1, l2, l3;
                LDSM4T(h0, h1, h2, h3, sb + AVH + vr);
                LDSM4T(l0, l1, l2, l3, sb + AVL + vr);
                uint32_t bh0[2] = {h0, h1}, bh1[2] = {h2, h3};
                uint32_t bl0[2] = {l0, l1}, bl1[2] = {l2, l3};
                MMA16816(oacc[2*p],   ph, bh0);
                MMA16816(oacc[2*p],   pl, bh0);
                MMA16816(oacc[2*p],   ph, bl0);
                MMA16816(oacc[2*p+1], ph, bh1);
                MMA16816(oacc[2*p+1], pl, bh1);
                MMA16816(oacc[2*p+1], ph, bl1);
            }
        }
        __syncthreads();
    }

    float inv0 = 1.0f / lrow0, inv1 = 1.0f / lrow1;
    size_t row0 = ((size_t)b * SEQ + qr0) * EMB + h * HD;
    #pragma unroll
    for (int nt = 0; nt < 8; nt++) {
        int d = nt * 8 + (lane & 3) * 2;
        float v0 = oacc[nt][0] * inv0, v1 = oacc[nt][1] * inv0;
        float v2 = oacc[nt][2] * inv1, v3 = oacc[nt][3] * inv1;
        float ra, rb;
        uint32_t H0 = packres(v0, v1, ra, rb), L0 = packbf(ra, rb);
        *(uint32_t*)(ch_g + row0 + d) = H0;
        *(uint32_t*)(cl_g + row0 + d) = L0;
        uint32_t H1 = packres(v2, v3, ra, rb), L1 = packbf(ra, rb);
        *(uint32_t*)(ch_g + row0 + (size_t)8 * EMB + d) = H1;
        *(uint32_t*)(cl_g + row0 + (size_t)8 * EMB + d) = L1;
    }
}

// ---------------------------------------------------------------------------
extern "C" void kernel_launch(void* const* d_in, const int* in_sizes, int n_in,
                              void* d_out, int out_size)
{
    const float* x  = (const float*)d_in[0];
    const float* w1 = (const float*)d_in[1];
    const float* b1 = (const float*)d_in[2];
    const float* w2 = (const float*)d_in[3];
    const float* b2 = (const float*)d_in[4];
    const float* rb = (const float*)d_in[5];
    float* out = (float*)d_out;

    __nv_bfloat16 *ah, *al, *bh, *bl, *qh, *ql, *kh, *kl, *vh, *vl;
    cudaGetSymbolAddress((void**)&ah, g_ah);
    cudaGetSymbolAddress((void**)&al, g_al);
    cudaGetSymbolAddress((void**)&bh, g_bh);
    cudaGetSymbolAddress((void**)&bl, g_bl);
    cudaGetSymbolAddress((void**)&qh, g_qh);
    cudaGetSymbolAddress((void**)&ql, g_ql);
    cudaGetSymbolAddress((void**)&kh, g_kh);
    cudaGetSymbolAddress((void**)&kl, g_kl);
    cudaGetSymbolAddress((void**)&vh, g_vh);
    cudaGetSymbolAddress((void**)&vl, g_vl);

    const int MM = BATCH * SEQ;
    const size_t gemm_shm = 2 * (size_t)STG;   // 81920 B
    cudaFuncSetAttribute(gemm_hmma<true>,  cudaFuncAttributeMaxDynamicSharedMemorySize, (int)gemm_shm);
    cudaFuncSetAttribute(gemm_hmma<false>, cudaFuncAttributeMaxDynamicSharedMemorySize, (int)gemm_shm);
    cudaFuncSetAttribute(attn_hmma, cudaFuncAttributeMaxDynamicSharedMemorySize, (int)ASMEM);

    bias_kernel<<<1, 96>>>(rb);

    {   // split x, w1
        int n4 = MM * EMB / 4;
        split_kernel<<<(n4 + 255) / 256, 256>>>(x, ah, al, n4);
        n4 = 3 * EMB * EMB / 4;
        split_kernel<<<(n4 + 255) / 256, 256>>>(w1, bh, bl, n4);
    }
    {   // QKV projection with fused per-head split epilogue
        dim3 g(3 * EMB / 128, MM / 128);
        gemm_hmma<true><<<g, 128, gemm_shm>>>(ah, al, bh, bl, b1, nullptr,
                                              qh, ql, kh, kl, vh, vl,
                                              MM, 3 * EMB, EMB);
    }
    {   // attention with fused ctx-split epilogue (writes ah/al)
        dim3 g(SEQ / 128, NH, BATCH);
        attn_hmma<<<g, 256, ASMEM>>>(qh, ql, kh, kl, vh, vl, ah, al);
    }
    {   // split w2; out projection
        int n4 = EMB * EMB / 4;
        split_kernel<<<(n4 + 255) / 256, 256>>>(w2, bh, bl, n4);
        dim3 g(EMB / 128, MM / 128);
        gemm_hmma<false><<<g, 128, gemm_shm>>>(ah, al, bh, bl, b2, out,
                                               nullptr, nullptr, nullptr, nullptr, nullptr, nullptr,
                                               MM, EMB, EMB);
    }
}